// round 2
// baseline (speedup 1.0000x reference)
#include <cuda_runtime.h>
#include <math.h>

// Problem constants
#define BB  4
#define SS  512
#define DD  512
#define HH  8
#define DHH 64
#define FFD 2048
#define LL  6
#define VV  32000
#define MM  (BB*SS)        // 2048 rows
#define QKVLD (3*DD)       // 1536

// ---------------- scratch (device globals; no allocation allowed) ----------
__device__ float g_x   [MM*DD];
__device__ float g_h   [MM*DD];
__device__ float g_a   [MM*DD];
__device__ float g_qkv [MM*3*DD];
__device__ float g_sc  [BB*HH*SS*SS];
__device__ float g_ao  [MM*DD];
__device__ float g_pr  [MM*DD];
__device__ float g_ff  [MM*FFD];
__device__ float g_dp  [MM];          // decoder pad mask (tokens==0)

// ---------------- embedding + positional encoding + pad mask ---------------
__global__ void embed_kernel(const int* __restrict__ tokens,
                             const float* __restrict__ emb,
                             float* __restrict__ x, float* __restrict__ depad)
{
    int row = blockIdx.x;            // 0..MM-1  (b*S + s)
    int s   = row & (SS-1);
    int tok = tokens[row];
    if (threadIdx.x == 0) depad[row] = (tok == 0) ? 1.0f : 0.0f;
    const float sq = sqrtf((float)DD);
    for (int d = threadIdx.x; d < DD; d += blockDim.x) {
        float i   = (float)((d >> 1) << 1) / (float)DD;
        float inv = powf(10000.0f, -i);
        float em  = (float)s * inv;
        float pe  = ((d & 1) == 0) ? sinf(em) : cosf(em);
        x[row*DD + d] = emb[(size_t)tok*DD + d] * sq + pe;
    }
}

// ---------------- generic tiled SGEMM:  C = A * W^T (+bias)(+relu) ---------
// A: [M,K] row-major (lda), W: [N,K] row-major (ldw), C: [M,N] (ldc)
// grid = (N/64, M/64), block = 256
template<int BIAS, int RELU>
__global__ void __launch_bounds__(256)
gemm_nt(const float* __restrict__ A, const float* __restrict__ W,
        const float* __restrict__ bias, float* __restrict__ C,
        int K, int lda, int ldw, int ldc)
{
    __shared__ float As[16][64];
    __shared__ float Ws[16][64];
    const int m0 = blockIdx.y * 64, n0 = blockIdx.x * 64;
    const int t  = threadIdx.x;
    const int lr = t >> 2, lc = (t & 3) << 2;     // loader: row 0..63, col 0..12
    const int tx = t & 15, ty = t >> 4;           // compute: 16x16 threads
    float acc[4][4] = {};
    const float* Ap = A + (size_t)(m0 + lr) * lda + lc;
    const float* Wp = W + (size_t)(n0 + lr) * ldw + lc;
    for (int k0 = 0; k0 < K; k0 += 16) {
        float4 av = *(const float4*)(Ap + k0);
        float4 wv = *(const float4*)(Wp + k0);
        As[lc+0][lr]=av.x; As[lc+1][lr]=av.y; As[lc+2][lr]=av.z; As[lc+3][lr]=av.w;
        Ws[lc+0][lr]=wv.x; Ws[lc+1][lr]=wv.y; Ws[lc+2][lr]=wv.z; Ws[lc+3][lr]=wv.w;
        __syncthreads();
        #pragma unroll
        for (int kk = 0; kk < 16; kk++) {
            float4 ra = *(const float4*)&As[kk][ty << 2];
            float4 rb = *(const float4*)&Ws[kk][tx << 2];
            float ar[4] = {ra.x, ra.y, ra.z, ra.w};
            float br[4] = {rb.x, rb.y, rb.z, rb.w};
            #pragma unroll
            for (int i = 0; i < 4; i++)
                #pragma unroll
                for (int j = 0; j < 4; j++)
                    acc[i][j] += ar[i] * br[j];
        }
        __syncthreads();
    }
    #pragma unroll
    for (int i = 0; i < 4; i++) {
        int m = m0 + (ty << 2) + i;
        #pragma unroll
        for (int j = 0; j < 4; j++) {
            int n = n0 + (tx << 2) + j;
            float v = acc[i][j];
            if (BIAS) v += bias[n];
            if (RELU) v = fmaxf(v, 0.0f);
            C[(size_t)m * ldc + n] = v;
        }
    }
}

// ---------------- attention scores:  s = Q K^T / 8 - mask*1e6 --------------
// Q rows at qkv[.., h*64], K rows at qkv[.., 512 + h*64]; mask: [B,S] floats.
// grid = (S/64, S/64, B*H)
template<int CAUSAL>
__global__ void __launch_bounds__(256)
attn_scores(const float* __restrict__ qkv, const float* __restrict__ mask,
            float* __restrict__ scores)
{
    __shared__ float Qs[16][64];
    __shared__ float Ks[16][64];
    const int z  = blockIdx.z, b = z >> 3, h = z & 7;
    const int q0 = blockIdx.y * 64, k0v = blockIdx.x * 64;
    const int t  = threadIdx.x;
    const int lr = t >> 2, lc = (t & 3) << 2;
    const int tx = t & 15, ty = t >> 4;
    const float* Q  = qkv + (size_t)(b*SS + q0 + lr) * QKVLD + h*DHH + lc;
    const float* Kv = qkv + (size_t)(b*SS + k0v + lr) * QKVLD + DD + h*DHH + lc;
    float acc[4][4] = {};
    for (int k0 = 0; k0 < DHH; k0 += 16) {
        float4 av = *(const float4*)(Q + k0);
        float4 wv = *(const float4*)(Kv + k0);
        Qs[lc+0][lr]=av.x; Qs[lc+1][lr]=av.y; Qs[lc+2][lr]=av.z; Qs[lc+3][lr]=av.w;
        Ks[lc+0][lr]=wv.x; Ks[lc+1][lr]=wv.y; Ks[lc+2][lr]=wv.z; Ks[lc+3][lr]=wv.w;
        __syncthreads();
        #pragma unroll
        for (int kk = 0; kk < 16; kk++) {
            float4 ra = *(const float4*)&Qs[kk][ty << 2];
            float4 rb = *(const float4*)&Ks[kk][tx << 2];
            float ar[4] = {ra.x, ra.y, ra.z, ra.w};
            float br[4] = {rb.x, rb.y, rb.z, rb.w};
            #pragma unroll
            for (int i = 0; i < 4; i++)
                #pragma unroll
                for (int j = 0; j < 4; j++)
                    acc[i][j] += ar[i] * br[j];
        }
        __syncthreads();
    }
    #pragma unroll
    for (int i = 0; i < 4; i++) {
        int qq = q0 + (ty << 2) + i;
        #pragma unroll
        for (int j = 0; j < 4; j++) {
            int kq = k0v + (tx << 2) + j;
            float mv = mask[b*SS + kq];
            if (CAUSAL && kq > qq) mv = 1.0f;     // max(de_pad, tri)
            scores[((size_t)z*SS + qq)*SS + kq] = acc[i][j] * 0.125f - mv * 1e6f;
        }
    }
}

// ---------------- row softmax over width 512 --------------------------------
__global__ void __launch_bounds__(256) softmax512(float* __restrict__ s)
{
    __shared__ float red[256];
    float* p = s + (size_t)blockIdx.x * SS;
    int t = threadIdx.x;
    float a = p[t], b = p[t + 256];
    red[t] = fmaxf(a, b);
    __syncthreads();
    for (int o = 128; o > 0; o >>= 1) { if (t < o) red[t] = fmaxf(red[t], red[t+o]); __syncthreads(); }
    float m = red[0];
    __syncthreads();
    float e0 = expf(a - m), e1 = expf(b - m);
    red[t] = e0 + e1;
    __syncthreads();
    for (int o = 128; o > 0; o >>= 1) { if (t < o) red[t] += red[t+o]; __syncthreads(); }
    float inv = 1.0f / red[0];
    p[t] = e0 * inv;
    p[t + 256] = e1 * inv;
}

// ---------------- attention * V :  O[b,q,h*64+d] = sum_k P[q,k] V[k,d] ------
// grid = (1, S/64, B*H)
__global__ void __launch_bounds__(256)
attn_av(const float* __restrict__ scores, const float* __restrict__ qkv,
        float* __restrict__ o)
{
    __shared__ float Ps[16][64];
    __shared__ float Vs[16][64];
    const int z  = blockIdx.z, b = z >> 3, h = z & 7;
    const int q0 = blockIdx.y * 64;
    const int t  = threadIdx.x;
    const int lr = t >> 2, lc = (t & 3) << 2;     // P loader
    const int vr = t >> 4, vc = (t & 15) << 2;    // V loader (16 x 64 direct)
    const int tx = t & 15, ty = t >> 4;
    const float* P = scores + ((size_t)z*SS + q0) * SS;
    const float* V = qkv + (size_t)(b*SS) * QKVLD + 2*DD + h*DHH;
    float acc[4][4] = {};
    for (int k0 = 0; k0 < SS; k0 += 16) {
        float4 pv = *(const float4*)(P + (size_t)lr*SS + k0 + lc);
        Ps[lc+0][lr]=pv.x; Ps[lc+1][lr]=pv.y; Ps[lc+2][lr]=pv.z; Ps[lc+3][lr]=pv.w;
        float4 vv = *(const float4*)(V + (size_t)(k0 + vr)*QKVLD + vc);
        *(float4*)&Vs[vr][vc] = vv;
        __syncthreads();
        #pragma unroll
        for (int kk = 0; kk < 16; kk++) {
            float4 ra = *(const float4*)&Ps[kk][ty << 2];
            float4 rb = *(const float4*)&Vs[kk][tx << 2];
            float ar[4] = {ra.x, ra.y, ra.z, ra.w};
            float br[4] = {rb.x, rb.y, rb.z, rb.w};
            #pragma unroll
            for (int i = 0; i < 4; i++)
                #pragma unroll
                for (int j = 0; j < 4; j++)
                    acc[i][j] += ar[i] * br[j];
        }
        __syncthreads();
    }
    #pragma unroll
    for (int i = 0; i < 4; i++)
        #pragma unroll
        for (int j = 0; j < 4; j++)
            o[(size_t)(b*SS + q0 + (ty<<2) + i) * DD + h*DHH + (tx<<2) + j] = acc[i][j];
}

// ---------------- fused residual add + LayerNorm ----------------------------
__global__ void __launch_bounds__(256)
add_ln(const float* __restrict__ x1, const float* __restrict__ x2,
       const float* __restrict__ g, const float* __restrict__ bb,
       float* __restrict__ y)
{
    __shared__ float red[256];
    const int row = blockIdx.x, t = threadIdx.x;
    const size_t base = (size_t)row * DD;
    float a = x1[base + t]       + x2[base + t];
    float c = x1[base + t + 256] + x2[base + t + 256];
    red[t] = a + c;
    __syncthreads();
    for (int o = 128; o > 0; o >>= 1) { if (t < o) red[t] += red[t+o]; __syncthreads(); }
    float mu = red[0] * (1.0f / DD);
    __syncthreads();
    float da = a - mu, dc = c - mu;
    red[t] = da*da + dc*dc;
    __syncthreads();
    for (int o = 128; o > 0; o >>= 1) { if (t < o) red[t] += red[t+o]; __syncthreads(); }
    float inv = rsqrtf(red[0] * (1.0f / DD) + 1e-6f);
    y[base + t]       = da * inv * g[t]       + bb[t];
    y[base + t + 256] = dc * inv * g[t + 256] + bb[t + 256];
}

// ---------------- launch ----------------------------------------------------
extern "C" void kernel_launch(void* const* d_in, const int* in_sizes, int n_in,
                              void* d_out, int out_size)
{
    const int*   tokens = (const int*)  d_in[0];
    const float* en_out = (const float*)d_in[1];
    const float* en_pad = (const float*)d_in[2];   // [B,1,1,S] -> [B,S]
    const float* emb    = (const float*)d_in[3];
    const float* sa_w   = (const float*)d_in[4];
    const float* sa_b   = (const float*)d_in[5];
    const float* ca_w   = (const float*)d_in[6];
    const float* ca_b   = (const float*)d_in[7];
    const float* ff_w1  = (const float*)d_in[8];
    const float* ff_b1  = (const float*)d_in[9];
    const float* ff_w2  = (const float*)d_in[10];
    const float* ff_b2  = (const float*)d_in[11];
    const float* ln_g   = (const float*)d_in[12];
    const float* ln_b   = (const float*)d_in[13];
    const float* out_w  = (const float*)d_in[14];
    const float* out_b  = (const float*)d_in[15];
    float* out = (float*)d_out;

    float *x, *h, *a, *qkv, *sc, *ao, *pr, *ff, *dp;
    cudaGetSymbolAddress((void**)&x,   g_x);
    cudaGetSymbolAddress((void**)&h,   g_h);
    cudaGetSymbolAddress((void**)&a,   g_a);
    cudaGetSymbolAddress((void**)&qkv, g_qkv);
    cudaGetSymbolAddress((void**)&sc,  g_sc);
    cudaGetSymbolAddress((void**)&ao,  g_ao);
    cudaGetSymbolAddress((void**)&pr,  g_pr);
    cudaGetSymbolAddress((void**)&ff,  g_ff);
    cudaGetSymbolAddress((void**)&dp,  g_dp);

    embed_kernel<<<MM, 256>>>(tokens, emb, x, dp);

    const dim3 gAttnS(SS/64, SS/64, BB*HH);   // scores
    const dim3 gAttnV(1,     SS/64, BB*HH);   // P @ V
    const int  nSoft = BB*HH*SS;

    for (int i = 0; i < LL; i++) {
        const float* saw = sa_w + (size_t)i*4*DD*DD;
        const float* sab = sa_b + (size_t)i*4*DD;
        const float* caw = ca_w + (size_t)i*4*DD*DD;
        const float* cab = ca_b + (size_t)i*4*DD;

        // ---- self attention ----
        gemm_nt<1,0><<<dim3(3*DD/64, MM/64), 256>>>(x,  saw,          sab,        qkv, DD, DD, DD, QKVLD);
        attn_scores<1><<<gAttnS, 256>>>(qkv, dp, sc);
        softmax512<<<nSoft, 256>>>(sc);
        attn_av<<<gAttnV, 256>>>(sc, qkv, ao);
        gemm_nt<1,0><<<dim3(DD/64, MM/64), 256>>>(ao, saw + 3*DD*DD, sab + 3*DD, pr,  DD, DD, DD, DD);
        add_ln<<<MM, 256>>>(x, pr, ln_g + (size_t)(i*3+0)*DD, ln_b + (size_t)(i*3+0)*DD, h);

        // ---- cross attention ----
        gemm_nt<1,0><<<dim3(DD/64,   MM/64), 256>>>(h,      caw,          cab,       qkv,      DD, DD, DD, QKVLD);
        gemm_nt<1,0><<<dim3(2*DD/64, MM/64), 256>>>(en_out, caw + DD*DD,  cab + DD,  qkv + DD, DD, DD, DD, QKVLD);
        attn_scores<0><<<gAttnS, 256>>>(qkv, en_pad, sc);
        softmax512<<<nSoft, 256>>>(sc);
        attn_av<<<gAttnV, 256>>>(sc, qkv, ao);
        gemm_nt<1,0><<<dim3(DD/64, MM/64), 256>>>(ao, caw + 3*DD*DD, cab + 3*DD, pr, DD, DD, DD, DD);
        add_ln<<<MM, 256>>>(h, pr, ln_g + (size_t)(i*3+1)*DD, ln_b + (size_t)(i*3+1)*DD, a);

        // ---- feed forward ----
        gemm_nt<1,1><<<dim3(FFD/64, MM/64), 256>>>(a,  ff_w1 + (size_t)i*FFD*DD, ff_b1 + (size_t)i*FFD, ff, DD,  DD,  DD,  FFD);
        gemm_nt<1,0><<<dim3(DD/64,  MM/64), 256>>>(ff, ff_w2 + (size_t)i*DD*FFD, ff_b2 + (size_t)i*DD,  pr, FFD, FFD, FFD, DD);
        add_ln<<<MM, 256>>>(a, pr, ln_g + (size_t)(i*3+2)*DD, ln_b + (size_t)(i*3+2)*DD, x);
    }

    // ---- final vocab projection ----
    gemm_nt<1,0><<<dim3(VV/64, MM/64), 256>>>(x, out_w, out_b, out, DD, DD, DD, VV);
}

// round 4
// speedup vs baseline: 1.4008x; 1.4008x over previous
#include <cuda_runtime.h>
#include <cuda_bf16.h>
#include <math.h>
#include <stdint.h>

typedef unsigned int u32; typedef unsigned long long u64;
#define BB 4
#define SS 512
#define DD 512
#define HH 8
#define DHH 64
#define FFD 2048
#define LL 6
#define VV 32000
#define MM (BB*SS)
#define QKVLD (3*DD)

__device__ float g_x[MM*DD], g_h[MM*DD], g_a[MM*DD], g_qkv[MM*3*DD];
__device__ float g_sc[BB*HH*SS*SS], g_pr[MM*DD], g_dp[MM];
#define NW_SA (LL*4*DD*DD)
#define NW_F1 (LL*FFD*DD)
#define NW_OUT (VV*DD)
__device__ __nv_bfloat16 g_wsa_h[NW_SA], g_wsa_l[NW_SA], g_wca_h[NW_SA], g_wca_l[NW_SA];
__device__ __nv_bfloat16 g_wf1_h[NW_F1], g_wf1_l[NW_F1], g_wf2_h[NW_F1], g_wf2_l[NW_F1];
__device__ __nv_bfloat16 g_wo_h[NW_OUT], g_wo_l[NW_OUT], g_en_h[MM*DD], g_en_l[MM*DD];
__device__ __nv_bfloat16 g_xh[MM*DD], g_xl[MM*DD], g_hh[MM*DD], g_hl2[MM*DD];
__device__ __nv_bfloat16 g_ah[MM*DD], g_al[MM*DD], g_aoh[MM*DD], g_aol[MM*DD];
__device__ __nv_bfloat16 g_ffh[MM*FFD], g_ffl[MM*FFD];

__device__ __forceinline__ u32 smem_u32(const void* p) {
    u32 a; asm("{ .reg .u64 t; cvta.to.shared.u64 t, %1; cvt.u32.u64 %0, t; }" : "=r"(a) : "l"(p)); return a;
}
__device__ __forceinline__ void ldsm4(u32& r0, u32& r1, u32& r2, u32& r3, u32 addr) {
    asm volatile("ldmatrix.sync.aligned.m8n8.x4.shared.b16 {%0,%1,%2,%3}, [%4];"
                 : "=r"(r0), "=r"(r1), "=r"(r2), "=r"(r3) : "r"(addr));
}
__device__ __forceinline__ void mma16816(float* d, const u32* a, const u32* b) {
    asm volatile("mma.sync.aligned.m16n8k16.row.col.f32.bf16.bf16.f32 "
                 "{%0,%1,%2,%3}, {%4,%5,%6,%7}, {%8,%9}, {%0,%1,%2,%3};"
                 : "+f"(d[0]), "+f"(d[1]), "+f"(d[2]), "+f"(d[3])
                 : "r"(a[0]), "r"(a[1]), "r"(a[2]), "r"(a[3]), "r"(b[0]), "r"(b[1]));
}
__device__ __forceinline__ void split_hl(float v, __nv_bfloat16& h, __nv_bfloat16& l) {
    h = __float2bfloat16(v); l = __float2bfloat16(v - __bfloat162float(h));
}

__global__ void cvt_hl(const float* __restrict__ s, __nv_bfloat16* __restrict__ hi,
                       __nv_bfloat16* __restrict__ lo, int n4) {
    int i = blockIdx.x*blockDim.x + threadIdx.x;
    if (i >= n4) return;
    float4 v = ((const float4*)s)[i];
    __nv_bfloat16 h, l;
    split_hl(v.x,h,l); hi[i*4+0]=h; lo[i*4+0]=l;
    split_hl(v.y,h,l); hi[i*4+1]=h; lo[i*4+1]=l;
    split_hl(v.z,h,l); hi[i*4+2]=h; lo[i*4+2]=l;
    split_hl(v.w,h,l); hi[i*4+3]=h; lo[i*4+3]=l;
}

// ======== HMMA split-3 GEMM: C[M,N] = A[M,K]*W[N,K]^T + bias ===============
// A ≈ Ah+Al, W ≈ Wh+Wl;  C = Ah·Wh + Ah·Wl + Al·Wh  (fp32 accum)
// CTA tile 128x128, BK=32, 8 warps of 64x32, double-buffered smem.
#define SPITCH 40
template<int RELU, int OUTHL>
__global__ void __launch_bounds__(256)
tgemm(const __nv_bfloat16* __restrict__ Ah, const __nv_bfloat16* __restrict__ Al,
      const __nv_bfloat16* __restrict__ Wh, const __nv_bfloat16* __restrict__ Wl,
      const float* __restrict__ bias, float* __restrict__ C,
      __nv_bfloat16* __restrict__ Ch, __nv_bfloat16* __restrict__ Cl, int K, int ldc)
{
    __shared__ __align__(16) __nv_bfloat16 As[2][128][SPITCH];
    __shared__ __align__(16) __nv_bfloat16 Ws[2][128][SPITCH];
    const int t = threadIdx.x, lane = t & 31, wid = t >> 5;
    const int m0 = blockIdx.y*128, n0 = blockIdx.x*128;
    const int wm = wid >> 2, wn = wid & 3;          // warp tile: 64(m) x 32(n)
    const int mbase = wm*64, nbase = wn*32;

    // ldmatrix per-lane offsets
    const int mat = lane >> 3, rowin = lane & 7;
    const int a_row = (mat & 1)*8 + rowin, a_col = (mat >> 1)*8;
    const int b_row = (mat >> 1)*8 + rowin, b_col = (mat & 1)*8;

    // gmem loader mapping: each thread loads 2 uint4 of A and 2 of W
    const int lrow = t >> 1, lcol = (t & 1) << 4;

    const int kc = K >> 5, nch = 3*kc;
    float acc[4][4][4];
    #pragma unroll
    for (int i = 0; i < 4; i++)
        #pragma unroll
        for (int j = 0; j < 4; j++)
            #pragma unroll
            for (int q = 0; q < 4; q++) acc[i][j][q] = 0.f;

    // prologue: chunk 0 -> buf 0
    {
        const __nv_bfloat16* as = Ah + (size_t)(m0+lrow)*K + lcol;
        const __nv_bfloat16* ws = Wh + (size_t)(n0+lrow)*K + lcol;
        *(uint4*)&As[0][lrow][lcol]   = *(const uint4*)as;
        *(uint4*)&As[0][lrow][lcol+8] = *(const uint4*)(as+8);
        *(uint4*)&Ws[0][lrow][lcol]   = *(const uint4*)ws;
        *(uint4*)&Ws[0][lrow][lcol+8] = *(const uint4*)(ws+8);
    }
    __syncthreads();

    for (int c = 0; c < nch; ++c) {
        const int buf = c & 1;
        uint4 ra0, ra1, rw0, rw1;
        const bool pf = (c+1 < nch);
        if (pf) {
            const int c1 = c+1, seg = c1/kc, kq = (c1 - seg*kc) << 5;
            const __nv_bfloat16* as = ((seg == 2) ? Al : Ah) + (size_t)(m0+lrow)*K + kq + lcol;
            const __nv_bfloat16* ws = ((seg == 1) ? Wl : Wh) + (size_t)(n0+lrow)*K + kq + lcol;
            ra0 = *(const uint4*)as; ra1 = *(const uint4*)(as+8);
            rw0 = *(const uint4*)ws; rw1 = *(const uint4*)(ws+8);
        }
        const u32 abase = smem_u32(&As[buf][0][0]);
        const u32 wbase = smem_u32(&Ws[buf][0][0]);
        #pragma unroll
        for (int ks = 0; ks < 2; ks++) {
            u32 af[4][4], bfr[2][4];
            #pragma unroll
            for (int mi = 0; mi < 4; mi++) {
                u32 ad = abase + (u32)(((mbase + mi*16 + a_row)*SPITCH + ks*16 + a_col)*2);
                ldsm4(af[mi][0], af[mi][1], af[mi][2], af[mi][3], ad);
            }
            #pragma unroll
            for (int g = 0; g < 2; g++) {
                u32 bd = wbase + (u32)(((nbase + g*16 + b_row)*SPITCH + ks*16 + b_col)*2);
                ldsm4(bfr[g][0], bfr[g][1], bfr[g][2], bfr[g][3], bd);
            }
            #pragma unroll
            for (int mi = 0; mi < 4; mi++)
                #pragma unroll
                for (int ni = 0; ni < 4; ni++)
                    mma16816(acc[mi][ni], af[mi], &bfr[ni >> 1][(ni & 1)*2]);
        }
        if (pf) {
            const int nb = buf ^ 1;
            *(uint4*)&As[nb][lrow][lcol]   = ra0;
            *(uint4*)&As[nb][lrow][lcol+8] = ra1;
            *(uint4*)&Ws[nb][lrow][lcol]   = rw0;
            *(uint4*)&Ws[nb][lrow][lcol+8] = rw1;
            __syncthreads();
        }
    }

    // epilogue
    const int r = lane >> 2, c2 = (lane & 3) << 1;
    #pragma unroll
    for (int mi = 0; mi < 4; mi++) {
        #pragma unroll
        for (int ni = 0; ni < 4; ni++) {
            const int m = m0 + mbase + mi*16 + r;
            const int n = n0 + nbase + ni*8 + c2;
            float b0 = bias[n], b1 = bias[n+1];
            float v0 = acc[mi][ni][0] + b0, v1 = acc[mi][ni][1] + b1;
            float v2 = acc[mi][ni][2] + b0, v3 = acc[mi][ni][3] + b1;
            if (RELU) { v0=fmaxf(v0,0.f); v1=fmaxf(v1,0.f); v2=fmaxf(v2,0.f); v3=fmaxf(v3,0.f); }
            if (OUTHL) {
                __nv_bfloat16 h, l;
                size_t i0 = (size_t)m*ldc + n, i1 = (size_t)(m+8)*ldc + n;
                split_hl(v0,h,l); Ch[i0]=h;   Cl[i0]=l;
                split_hl(v1,h,l); Ch[i0+1]=h; Cl[i0+1]=l;
                split_hl(v2,h,l); Ch[i1]=h;   Cl[i1]=l;
                split_hl(v3,h,l); Ch[i1+1]=h; Cl[i1+1]=l;
            } else {
                *(float2*)(C + (size_t)m*ldc + n)     = make_float2(v0, v1);
                *(float2*)(C + (size_t)(m+8)*ldc + n) = make_float2(v2, v3);
            }
        }
    }
}

// ---------------- embedding ----------------
__global__ void embed_kernel(const int* __restrict__ tokens, const float* __restrict__ emb,
                             float* __restrict__ x, __nv_bfloat16* __restrict__ xh,
                             __nv_bfloat16* __restrict__ xl, float* __restrict__ depad)
{
    int row = blockIdx.x, s = row & (SS-1), tok = tokens[row];
    if (threadIdx.x == 0) depad[row] = (tok == 0) ? 1.0f : 0.0f;
    const float sq = sqrtf((float)DD);
    for (int d = threadIdx.x; d < DD; d += blockDim.x) {
        float i = (float)((d >> 1) << 1)/(float)DD;
        float em = (float)s*powf(10000.0f, -i);
        float pe = ((d & 1) == 0) ? sinf(em) : cosf(em);
        float v = emb[(size_t)tok*DD + d]*sq + pe;
        x[(size_t)row*DD + d] = v;
        __nv_bfloat16 h, l; split_hl(v, h, l);
        xh[(size_t)row*DD + d] = h; xl[(size_t)row*DD + d] = l;
    }
}

// ---------------- attention scores ----------------
template<int CAUSAL>
__global__ void __launch_bounds__(256)
attn_scores(const float* __restrict__ qkv, const float* __restrict__ mask, float* __restrict__ scores)
{
    __shared__ float Qs[16][64], Ks[16][64];
    const int z = blockIdx.z, b = z >> 3, h = z & 7;
    const int q0 = blockIdx.y*64, k0v = blockIdx.x*64;
    const int t = threadIdx.x, lr = t >> 2, lc = (t & 3) << 2, tx = t & 15, ty = t >> 4;
    const float* Q  = qkv + (size_t)(b*SS + q0 + lr)*QKVLD + h*DHH + lc;
    const float* Kv = qkv + (size_t)(b*SS + k0v + lr)*QKVLD + DD + h*DHH + lc;
    float acc[4][4] = {};
    for (int k0 = 0; k0 < DHH; k0 += 16) {
        float4 av = *(const float4*)(Q + k0), wv = *(const float4*)(Kv + k0);
        Qs[lc+0][lr]=av.x; Qs[lc+1][lr]=av.y; Qs[lc+2][lr]=av.z; Qs[lc+3][lr]=av.w;
        Ks[lc+0][lr]=wv.x; Ks[lc+1][lr]=wv.y; Ks[lc+2][lr]=wv.z; Ks[lc+3][lr]=wv.w;
        __syncthreads();
        #pragma unroll
        for (int kk = 0; kk < 16; kk++) {
            float4 ra = *(const float4*)&Qs[kk][ty << 2], rb = *(const float4*)&Ks[kk][tx << 2];
            float ar[4] = {ra.x,ra.y,ra.z,ra.w}, br[4] = {rb.x,rb.y,rb.z,rb.w};
            #pragma unroll
            for (int i = 0; i < 4; i++)
                #pragma unroll
                for (int j = 0; j < 4; j++) acc[i][j] += ar[i]*br[j];
        }
        __syncthreads();
    }
    #pragma unroll
    for (int i = 0; i < 4; i++) {
        int qq = q0 + (ty << 2) + i;
        #pragma unroll
        for (int j = 0; j < 4; j++) {
            int kq = k0v + (tx << 2) + j;
            float mv = mask[b*SS + kq];
            if (CAUSAL && kq > qq) mv = 1.0f;
            scores[((size_t)z*SS + qq)*SS + kq] = acc[i][j]*0.125f - mv*1e6f;
        }
    }
}

// ---------------- softmax ----------------
__global__ void __launch_bounds__(256) softmax512(float* __restrict__ s)
{
    __shared__ float red[256];
    float* p = s + (size_t)blockIdx.x*SS;
    int t = threadIdx.x;
    float a = p[t], b = p[t+256];
    red[t] = fmaxf(a, b); __syncthreads();
    for (int o = 128; o > 0; o >>= 1) { if (t < o) red[t] = fmaxf(red[t], red[t+o]); __syncthreads(); }
    float m = red[0]; __syncthreads();
    float e0 = expf(a - m), e1 = expf(b - m);
    red[t] = e0 + e1; __syncthreads();
    for (int o = 128; o > 0; o >>= 1) { if (t < o) red[t] += red[t+o]; __syncthreads(); }
    float inv = 1.0f/red[0];
    p[t] = e0*inv; p[t+256] = e1*inv;
}

// ---------------- attention AV (bf16 hi/lo out) ----------------
__global__ void __launch_bounds__(256)
attn_av(const float* __restrict__ scores, const float* __restrict__ qkv,
        __nv_bfloat16* __restrict__ oh, __nv_bfloat16* __restrict__ ol)
{
    __shared__ float Ps[16][64], Vs[16][64];
    const int z = blockIdx.z, b = z >> 3, h = z & 7;
    const int q0 = blockIdx.y*64;
    const int t = threadIdx.x, lr = t >> 2, lc = (t & 3) << 2;
    const int vr = t >> 4, vc = (t & 15) << 2, tx = t & 15, ty = t >> 4;
    const float* P = scores + ((size_t)z*SS + q0)*SS;
    const float* V = qkv + (size_t)(b*SS)*QKVLD + 2*DD + h*DHH;
    float acc[4][4] = {};
    for (int k0 = 0; k0 < SS; k0 += 16) {
        float4 pv = *(const float4*)(P + (size_t)lr*SS + k0 + lc);
        Ps[lc+0][lr]=pv.x; Ps[lc+1][lr]=pv.y; Ps[lc+2][lr]=pv.z; Ps[lc+3][lr]=pv.w;
        *(float4*)&Vs[vr][vc] = *(const float4*)(V + (size_t)(k0 + vr)*QKVLD + vc);
        __syncthreads();
        #pragma unroll
        for (int kk = 0; kk < 16; kk++) {
            float4 ra = *(const float4*)&Ps[kk][ty << 2], rb = *(const float4*)&Vs[kk][tx << 2];
            float ar[4] = {ra.x,ra.y,ra.z,ra.w}, br[4] = {rb.x,rb.y,rb.z,rb.w};
            #pragma unroll
            for (int i = 0; i < 4; i++)
                #pragma unroll
                for (int j = 0; j < 4; j++) acc[i][j] += ar[i]*br[j];
        }
        __syncthreads();
    }
    #pragma unroll
    for (int i = 0; i < 4; i++)
        #pragma unroll
        for (int j = 0; j < 4; j++) {
            size_t idx = (size_t)(b*SS + q0 + (ty<<2) + i)*DD + h*DHH + (tx<<2) + j;
            __nv_bfloat16 hh, ll; split_hl(acc[i][j], hh, ll);
            oh[idx] = hh; ol[idx] = ll;
        }
}

// ---------------- residual add + LayerNorm (+hi/lo) ----------------
__global__ void __launch_bounds__(256)
add_ln(const float* __restrict__ x1, const float* __restrict__ x2,
       const float* __restrict__ g, const float* __restrict__ bb,
       float* __restrict__ y, __nv_bfloat16* __restrict__ yh, __nv_bfloat16* __restrict__ yl)
{
    __shared__ float red[256];
    const int row = blockIdx.x, t = threadIdx.x;
    const size_t base = (size_t)row*DD;
    float a = x1[base+t] + x2[base+t];
    float c = x1[base+t+256] + x2[base+t+256];
    red[t] = a + c; __syncthreads();
    for (int o = 128; o > 0; o >>= 1) { if (t < o) red[t] += red[t+o]; __syncthreads(); }
    float mu = red[0]*(1.0f/DD); __syncthreads();
    float da = a - mu, dc = c - mu;
    red[t] = da*da + dc*dc; __syncthreads();
    for (int o = 128; o > 0; o >>= 1) { if (t < o) red[t] += red[t+o]; __syncthreads(); }
    float inv = rsqrtf(red[0]*(1.0f/DD) + 1e-6f);
    float v0 = da*inv*g[t] + bb[t], v1 = dc*inv*g[t+256] + bb[t+256];
    y[base+t] = v0; y[base+t+256] = v1;
    __nv_bfloat16 hh, ll;
    split_hl(v0, hh, ll); yh[base+t] = hh;     yl[base+t] = ll;
    split_hl(v1, hh, ll); yh[base+t+256] = hh; yl[base+t+256] = ll;
}

// ---------------- launch ----------------
extern "C" void kernel_launch(void* const* d_in, const int* in_sizes, int n_in,
                              void* d_out, int out_size)
{
    const int*   tokens = (const int*)d_in[0];
    const float* en_out = (const float*)d_in[1];
    const float* en_pad = (const float*)d_in[2];
    const float* emb    = (const float*)d_in[3];
    const float* sa_w = (const float*)d_in[4],  *sa_b = (const float*)d_in[5];
    const float* ca_w = (const float*)d_in[6],  *ca_b = (const float*)d_in[7];
    const float* ff_w1 = (const float*)d_in[8], *ff_b1 = (const float*)d_in[9];
    const float* ff_w2 = (const float*)d_in[10],*ff_b2 = (const float*)d_in[11];
    const float* ln_g = (const float*)d_in[12], *ln_b = (const float*)d_in[13];
    const float* out_w = (const float*)d_in[14],*out_b = (const float*)d_in[15];
    float* out = (float*)d_out;

    float *x,*h,*a,*qkv,*sc,*pr,*dp;
    cudaGetSymbolAddress((void**)&x,g_x); cudaGetSymbolAddress((void**)&h,g_h);
    cudaGetSymbolAddress((void**)&a,g_a); cudaGetSymbolAddress((void**)&qkv,g_qkv);
    cudaGetSymbolAddress((void**)&sc,g_sc); cudaGetSymbolAddress((void**)&pr,g_pr);
    cudaGetSymbolAddress((void**)&dp,g_dp);
    __nv_bfloat16 *wsah,*wsal,*wcah,*wcal,*wf1h,*wf1l,*wf2h,*wf2l,*woh,*wol,*enh,*enl;
    __nv_bfloat16 *xh,*xl,*hh,*hl,*ah,*al,*aoh,*aol,*ffh,*ffl;
    cudaGetSymbolAddress((void**)&wsah,g_wsa_h); cudaGetSymbolAddress((void**)&wsal,g_wsa_l);
    cudaGetSymbolAddress((void**)&wcah,g_wca_h); cudaGetSymbolAddress((void**)&wcal,g_wca_l);
    cudaGetSymbolAddress((void**)&wf1h,g_wf1_h); cudaGetSymbolAddress((void**)&wf1l,g_wf1_l);
    cudaGetSymbolAddress((void**)&wf2h,g_wf2_h); cudaGetSymbolAddress((void**)&wf2l,g_wf2_l);
    cudaGetSymbolAddress((void**)&woh,g_wo_h);   cudaGetSymbolAddress((void**)&wol,g_wo_l);
    cudaGetSymbolAddress((void**)&enh,g_en_h);   cudaGetSymbolAddress((void**)&enl,g_en_l);
    cudaGetSymbolAddress((void**)&xh,g_xh);   cudaGetSymbolAddress((void**)&xl,g_xl);
    cudaGetSymbolAddress((void**)&hh,g_hh);   cudaGetSymbolAddress((void**)&hl,g_hl2);
    cudaGetSymbolAddress((void**)&ah,g_ah);   cudaGetSymbolAddress((void**)&al,g_al);
    cudaGetSymbolAddress((void**)&aoh,g_aoh); cudaGetSymbolAddress((void**)&aol,g_aol);
    cudaGetSymbolAddress((void**)&ffh,g_ffh); cudaGetSymbolAddress((void**)&ffl,g_ffl);

    cvt_hl<<<NW_SA/4/256, 256>>>(sa_w, wsah, wsal, NW_SA/4);
    cvt_hl<<<NW_SA/4/256, 256>>>(ca_w, wcah, wcal, NW_SA/4);
    cvt_hl<<<NW_F1/4/256, 256>>>(ff_w1, wf1h, wf1l, NW_F1/4);
    cvt_hl<<<NW_F1/4/256, 256>>>(ff_w2, wf2h, wf2l, NW_F1/4);
    cvt_hl<<<NW_OUT/4/256, 256>>>(out_w, woh, wol, NW_OUT/4);
    cvt_hl<<<MM*DD/4/256, 256>>>(en_out, enh, enl, MM*DD/4);

    embed_kernel<<<MM, 256>>>(tokens, emb, x, xh, xl, dp);

    const dim3 gS(SS/64, SS/64, BB*HH), gV(1, SS/64, BB*HH);
    for (int i = 0; i < LL; i++) {
        const size_t w4 = (size_t)i*4*DD*DD, b4 = (size_t)i*4*DD;
        // self attention
        tgemm<0,0><<<dim3(QKVLD/128, MM/128), 256>>>(
            xh, xl, wsah+w4, wsal+w4, sa_b+b4, qkv, 0, 0, DD, QKVLD);
        attn_scores<1><<<gS, 256>>>(qkv, dp, sc);
        softmax512<<<BB*HH*SS, 256>>>(sc);
        attn_av<<<gV, 256>>>(sc, qkv, aoh, aol);
        tgemm<0,0><<<dim3(DD/128, MM/128), 256>>>(
            aoh, aol, wsah+w4+3*DD*DD, wsal+w4+3*DD*DD, sa_b+b4+3*DD, pr, 0, 0, DD, DD);
        add_ln<<<MM, 256>>>(x, pr, ln_g+(size_t)(i*3+0)*DD, ln_b+(size_t)(i*3+0)*DD, h, hh, hl);
        // cross attention
        tgemm<0,0><<<dim3(DD/128, MM/128), 256>>>(
            hh, hl, wcah+w4, wcal+w4, ca_b+b4, qkv, 0, 0, DD, QKVLD);
        tgemm<0,0><<<dim3(2*DD/128, MM/128), 256>>>(
            enh, enl, wcah+w4+DD*DD, wcal+w4+DD*DD, ca_b+b4+DD, qkv+DD, 0, 0, DD, QKVLD);
        attn_scores<0><<<gS, 256>>>(qkv, en_pad, sc);
        softmax512<<<BB*HH*SS, 256>>>(sc);
        attn_av<<<gV, 256>>>(sc, qkv, aoh, aol);
        tgemm<0,0><<<dim3(DD/128, MM/128), 256>>>(
            aoh, aol, wcah+w4+3*DD*DD, wcal+w4+3*DD*DD, ca_b+b4+3*DD, pr, 0, 0, DD, DD);
        add_ln<<<MM, 256>>>(h, pr, ln_g+(size_t)(i*3+1)*DD, ln_b+(size_t)(i*3+1)*DD, a, ah, al);
        // feed forward
        tgemm<1,1><<<dim3(FFD/128, MM/128), 256>>>(
            ah, al, wf1h+(size_t)i*FFD*DD, wf1l+(size_t)i*FFD*DD, ff_b1+(size_t)i*FFD,
            0, ffh, ffl, DD, FFD);
        tgemm<0,0><<<dim3(DD/128, MM/128), 256>>>(
            ffh, ffl, wf2h+(size_t)i*FFD*DD, wf2l+(size_t)i*FFD*DD, ff_b2+(size_t)i*DD,
            pr, 0, 0, FFD, DD);
        add_ln<<<MM, 256>>>(a, pr, ln_g+(size_t)(i*3+2)*DD, ln_b+(size_t)(i*3+2)*DD, x, xh, xl);
    }
    tgemm<0,0><<<dim3(VV/128, MM/128), 256>>>(
        xh, xl, woh, wol, out_b, out, 0, 0, DD, VV);
}

// round 5
// speedup vs baseline: 1.6096x; 1.1490x over previous
#include <cuda_runtime.h>
#include <cuda_bf16.h>
#include <math.h>
#include <stdint.h>

typedef unsigned int u32; typedef unsigned long long u64;
#define BB 4
#define SS 512
#define DD 512
#define HH 8
#define DHH 64
#define FFD 2048
#define LL 6
#define VV 32000
#define MM (BB*SS)
#define QKVLD (3*DD)

__device__ float g_x[MM*DD], g_h[MM*DD], g_a[MM*DD], g_qkv[MM*3*DD];
__device__ float g_sc[BB*HH*SS*SS], g_pr[MM*DD], g_dp[MM];
#define NW_SA (LL*4*DD*DD)
#define NW_F1 (LL*FFD*DD)
#define NW_OUT (VV*DD)
__device__ __nv_bfloat16 g_wsa_h[NW_SA], g_wsa_l[NW_SA], g_wca_h[NW_SA], g_wca_l[NW_SA];
__device__ __nv_bfloat16 g_wf1_h[NW_F1], g_wf1_l[NW_F1], g_wf2_h[NW_F1], g_wf2_l[NW_F1];
__device__ __nv_bfloat16 g_wo_h[NW_OUT], g_wo_l[NW_OUT], g_en_h[MM*DD], g_en_l[MM*DD];
__device__ __nv_bfloat16 g_xh[MM*DD], g_xl[MM*DD], g_hh[MM*DD], g_hl2[MM*DD];
__device__ __nv_bfloat16 g_ah[MM*DD], g_al[MM*DD], g_aoh[MM*DD], g_aol[MM*DD];
__device__ __nv_bfloat16 g_ffh[MM*FFD], g_ffl[MM*FFD];

__device__ __forceinline__ u32 smem_u32(const void* p) {
    u32 a; asm("{ .reg .u64 t; cvta.to.shared.u64 t, %1; cvt.u32.u64 %0, t; }" : "=r"(a) : "l"(p)); return a;
}
__device__ __forceinline__ void ldsm4(u32& r0, u32& r1, u32& r2, u32& r3, u32 addr) {
    asm volatile("ldmatrix.sync.aligned.m8n8.x4.shared.b16 {%0,%1,%2,%3}, [%4];"
                 : "=r"(r0), "=r"(r1), "=r"(r2), "=r"(r3) : "r"(addr));
}
__device__ __forceinline__ void mma16816(float* d, const u32* a, const u32* b) {
    asm volatile("mma.sync.aligned.m16n8k16.row.col.f32.bf16.bf16.f32 "
                 "{%0,%1,%2,%3}, {%4,%5,%6,%7}, {%8,%9}, {%0,%1,%2,%3};"
                 : "+f"(d[0]), "+f"(d[1]), "+f"(d[2]), "+f"(d[3])
                 : "r"(a[0]), "r"(a[1]), "r"(a[2]), "r"(a[3]), "r"(b[0]), "r"(b[1]));
}
__device__ __forceinline__ void cpa16(u32 saddr, const void* gaddr) {
    asm volatile("cp.async.cg.shared.global [%0], [%1], 16;" :: "r"(saddr), "l"(gaddr));
}
__device__ __forceinline__ void cpa_commit() { asm volatile("cp.async.commit_group;"); }
__device__ __forceinline__ void cpa_wait1()  { asm volatile("cp.async.wait_group 1;"); }
__device__ __forceinline__ void split_hl(float v, __nv_bfloat16& h, __nv_bfloat16& l) {
    h = __float2bfloat16(v); l = __float2bfloat16(v - __bfloat162float(h));
}

__global__ void cvt_hl(const float* __restrict__ s, __nv_bfloat16* __restrict__ hi,
                       __nv_bfloat16* __restrict__ lo, int n4) {
    int i = blockIdx.x*blockDim.x + threadIdx.x;
    if (i >= n4) return;
    float4 v = ((const float4*)s)[i];
    __nv_bfloat16 h, l;
    split_hl(v.x,h,l); hi[i*4+0]=h; lo[i*4+0]=l;
    split_hl(v.y,h,l); hi[i*4+1]=h; lo[i*4+1]=l;
    split_hl(v.z,h,l); hi[i*4+2]=h; lo[i*4+2]=l;
    split_hl(v.w,h,l); hi[i*4+3]=h; lo[i*4+3]=l;
}

// ======== HMMA split-3 GEMM, cp.async 3-stage: C = A*W^T + bias =============
#define SPITCH 40
#define TG_STAGES 3
#define TILEE (128*SPITCH)                    // elements per (A or W) tile buf
#define TG_DSMEM (TG_STAGES*2*TILEE*2)        // bytes
template<int RELU, int OUTHL>
__global__ void __launch_bounds__(256)
tgemm(const __nv_bfloat16* __restrict__ Ah, const __nv_bfloat16* __restrict__ Al,
      const __nv_bfloat16* __restrict__ Wh, const __nv_bfloat16* __restrict__ Wl,
      const float* __restrict__ bias, float* __restrict__ C,
      __nv_bfloat16* __restrict__ Ch, __nv_bfloat16* __restrict__ Cl, int K, int ldc)
{
    extern __shared__ __align__(16) __nv_bfloat16 sm[];  // [S][2][128][SPITCH]
    const int t = threadIdx.x, lane = t & 31, wid = t >> 5;
    const int m0 = blockIdx.y*128, n0 = blockIdx.x*128;
    const int wm = wid >> 2, wn = wid & 3;
    const int mbase = wm*64, nbase = wn*32;
    const int mat = lane >> 3, rowin = lane & 7;
    const int a_row = (mat & 1)*8 + rowin, a_col = (mat >> 1)*8;
    const int b_row = (mat >> 1)*8 + rowin, b_col = (mat & 1)*8;
    const int lrow = t >> 1, lcol = (t & 1) << 4;
    const int kc = K >> 5, nch = 3*kc;

    const u32 sdst_a = smem_u32(&sm[0]) + (u32)((lrow*SPITCH + lcol)*2);
    const u32 sdst_w = sdst_a + (u32)(TILEE*2);

    float acc[4][4][4];
    #pragma unroll
    for (int i = 0; i < 4; i++)
        #pragma unroll
        for (int j = 0; j < 4; j++)
            #pragma unroll
            for (int q = 0; q < 4; q++) acc[i][j][q] = 0.f;

    // issue chunk c into stage c%S
    auto issue = [&](int c) {
        const int s = c % TG_STAGES;
        const int seg = c / kc, kq = (c - seg*kc) << 5;
        const __nv_bfloat16* as = ((seg == 2) ? Al : Ah) + (size_t)(m0+lrow)*K + kq + lcol;
        const __nv_bfloat16* ws = ((seg == 1) ? Wl : Wh) + (size_t)(n0+lrow)*K + kq + lcol;
        const u32 da = sdst_a + (u32)(s*2*TILEE*2);
        const u32 dw = sdst_w + (u32)(s*2*TILEE*2);
        cpa16(da,      as);
        cpa16(da + 16, as + 8);
        cpa16(dw,      ws);
        cpa16(dw + 16, ws + 8);
    };

    #pragma unroll
    for (int c = 0; c < TG_STAGES-1; c++) { issue(c); cpa_commit(); }

    for (int c = 0; c < nch; ++c) {
        cpa_wait1();
        __syncthreads();
        const int s = c % TG_STAGES;
        const u32 abase = smem_u32(&sm[0]) + (u32)(s*2*TILEE*2);
        const u32 wbase = abase + (u32)(TILEE*2);
        #pragma unroll
        for (int ks = 0; ks < 2; ks++) {
            u32 af[4][4], bfr[2][4];
            #pragma unroll
            for (int mi = 0; mi < 4; mi++) {
                u32 ad = abase + (u32)(((mbase + mi*16 + a_row)*SPITCH + ks*16 + a_col)*2);
                ldsm4(af[mi][0], af[mi][1], af[mi][2], af[mi][3], ad);
            }
            #pragma unroll
            for (int g = 0; g < 2; g++) {
                u32 bd = wbase + (u32)(((nbase + g*16 + b_row)*SPITCH + ks*16 + b_col)*2);
                ldsm4(bfr[g][0], bfr[g][1], bfr[g][2], bfr[g][3], bd);
            }
            #pragma unroll
            for (int mi = 0; mi < 4; mi++)
                #pragma unroll
                for (int ni = 0; ni < 4; ni++)
                    mma16816(acc[mi][ni], af[mi], &bfr[ni >> 1][(ni & 1)*2]);
        }
        const int cn = c + TG_STAGES - 1;
        if (cn < nch) issue(cn);
        cpa_commit();
    }

    const int r = lane >> 2, c2 = (lane & 3) << 1;
    #pragma unroll
    for (int mi = 0; mi < 4; mi++) {
        #pragma unroll
        for (int ni = 0; ni < 4; ni++) {
            const int m = m0 + mbase + mi*16 + r;
            const int n = n0 + nbase + ni*8 + c2;
            float b0 = bias[n], b1 = bias[n+1];
            float v0 = acc[mi][ni][0] + b0, v1 = acc[mi][ni][1] + b1;
            float v2 = acc[mi][ni][2] + b0, v3 = acc[mi][ni][3] + b1;
            if (RELU) { v0=fmaxf(v0,0.f); v1=fmaxf(v1,0.f); v2=fmaxf(v2,0.f); v3=fmaxf(v3,0.f); }
            if (OUTHL) {
                __nv_bfloat16 h, l;
                size_t i0 = (size_t)m*ldc + n, i1 = (size_t)(m+8)*ldc + n;
                split_hl(v0,h,l); Ch[i0]=h;   Cl[i0]=l;
                split_hl(v1,h,l); Ch[i0+1]=h; Cl[i0+1]=l;
                split_hl(v2,h,l); Ch[i1]=h;   Cl[i1]=l;
                split_hl(v3,h,l); Ch[i1+1]=h; Cl[i1+1]=l;
            } else {
                *(float2*)(C + (size_t)m*ldc + n)     = make_float2(v0, v1);
                *(float2*)(C + (size_t)(m+8)*ldc + n) = make_float2(v2, v3);
            }
        }
    }
}

// ---------------- embedding ----------------
__global__ void embed_kernel(const int* __restrict__ tokens, const float* __restrict__ emb,
                             float* __restrict__ x, __nv_bfloat16* __restrict__ xh,
                             __nv_bfloat16* __restrict__ xl, float* __restrict__ depad)
{
    int row = blockIdx.x, s = row & (SS-1), tok = tokens[row];
    if (threadIdx.x == 0) depad[row] = (tok == 0) ? 1.0f : 0.0f;
    const float sq = sqrtf((float)DD);
    for (int d = threadIdx.x; d < DD; d += blockDim.x) {
        float i = (float)((d >> 1) << 1)/(float)DD;
        float em = (float)s*powf(10000.0f, -i);
        float pe = ((d & 1) == 0) ? sinf(em) : cosf(em);
        float v = emb[(size_t)tok*DD + d]*sq + pe;
        x[(size_t)row*DD + d] = v;
        __nv_bfloat16 h, l; split_hl(v, h, l);
        xh[(size_t)row*DD + d] = h; xl[(size_t)row*DD + d] = l;
    }
}

// ---------------- attention scores ----------------
template<int CAUSAL>
__global__ void __launch_bounds__(256)
attn_scores(const float* __restrict__ qkv, const float* __restrict__ mask, float* __restrict__ scores)
{
    __shared__ float Qs[16][64], Ks[16][64];
    const int z = blockIdx.z, b = z >> 3, h = z & 7;
    const int q0 = blockIdx.y*64, k0v = blockIdx.x*64;
    const int t = threadIdx.x, lr = t >> 2, lc = (t & 3) << 2, tx = t & 15, ty = t >> 4;
    const float* Q  = qkv + (size_t)(b*SS + q0 + lr)*QKVLD + h*DHH + lc;
    const float* Kv = qkv + (size_t)(b*SS + k0v + lr)*QKVLD + DD + h*DHH + lc;
    float acc[4][4] = {};
    for (int k0 = 0; k0 < DHH; k0 += 16) {
        float4 av = *(const float4*)(Q + k0), wv = *(const float4*)(Kv + k0);
        Qs[lc+0][lr]=av.x; Qs[lc+1][lr]=av.y; Qs[lc+2][lr]=av.z; Qs[lc+3][lr]=av.w;
        Ks[lc+0][lr]=wv.x; Ks[lc+1][lr]=wv.y; Ks[lc+2][lr]=wv.z; Ks[lc+3][lr]=wv.w;
        __syncthreads();
        #pragma unroll
        for (int kk = 0; kk < 16; kk++) {
            float4 ra = *(const float4*)&Qs[kk][ty << 2], rb = *(const float4*)&Ks[kk][tx << 2];
            float ar[4] = {ra.x,ra.y,ra.z,ra.w}, br[4] = {rb.x,rb.y,rb.z,rb.w};
            #pragma unroll
            for (int i = 0; i < 4; i++)
                #pragma unroll
                for (int j = 0; j < 4; j++) acc[i][j] += ar[i]*br[j];
        }
        __syncthreads();
    }
    #pragma unroll
    for (int i = 0; i < 4; i++) {
        int qq = q0 + (ty << 2) + i;
        #pragma unroll
        for (int j = 0; j < 4; j++) {
            int kq = k0v + (tx << 2) + j;
            float mv = mask[b*SS + kq];
            if (CAUSAL && kq > qq) mv = 1.0f;
            scores[((size_t)z*SS + qq)*SS + kq] = acc[i][j]*0.125f - mv*1e6f;
        }
    }
}

// ------- attn AV with fused softmax (bf16 hi/lo out) ------------------------
__global__ void __launch_bounds__(256)
attn_av_sm(const float* __restrict__ S, const float* __restrict__ qkv,
           __nv_bfloat16* __restrict__ oh, __nv_bfloat16* __restrict__ ol)
{
    __shared__ float Ps[16][64], Vs[16][64];
    __shared__ float rowm[64], rowinv[64];
    __shared__ float pm[64][4], psum[64][4];
    const int z = blockIdx.z, b = z >> 3, h = z & 7;
    const int q0 = blockIdx.y*64;
    const int t = threadIdx.x;

    // pass 1: row max & exp-sum (4 threads/row, 128 cols each)
    {
        int r = t >> 2, cseg = (t & 3)*128;
        const float* p = S + ((size_t)z*SS + q0 + r)*SS + cseg;
        float m = -1e30f, s = 0.f;
        #pragma unroll 4
        for (int i = 0; i < 128; i += 4) {
            float4 v = *(const float4*)(p + i);
            float mx = fmaxf(fmaxf(v.x, v.y), fmaxf(v.z, v.w));
            if (mx > m) { s *= expf(m - mx); m = mx; }
            s += expf(v.x-m) + expf(v.y-m) + expf(v.z-m) + expf(v.w-m);
        }
        pm[r][t & 3] = m; psum[r][t & 3] = s;
    }
    __syncthreads();
    if (t < 64) {
        float m0 = pm[t][0], m1 = pm[t][1], m2 = pm[t][2], m3 = pm[t][3];
        float M = fmaxf(fmaxf(m0, m1), fmaxf(m2, m3));
        float sm = psum[t][0]*expf(m0-M) + psum[t][1]*expf(m1-M)
                 + psum[t][2]*expf(m2-M) + psum[t][3]*expf(m3-M);
        rowm[t] = M; rowinv[t] = 1.0f/sm;
    }
    __syncthreads();

    // pass 2: O = exp(S - rowm) @ V
    const int lr = t >> 2, lc = (t & 3) << 2;
    const int vr = t >> 4, vc = (t & 15) << 2, tx = t & 15, ty = t >> 4;
    const float* P = S + ((size_t)z*SS + q0)*SS;
    const float* V = qkv + (size_t)(b*SS)*QKVLD + 2*DD + h*DHH;
    const float rm = rowm[lr];
    float acc[4][4] = {};
    for (int k0 = 0; k0 < SS; k0 += 16) {
        float4 pv = *(const float4*)(P + (size_t)lr*SS + k0 + lc);
        Ps[lc+0][lr] = expf(pv.x - rm);
        Ps[lc+1][lr] = expf(pv.y - rm);
        Ps[lc+2][lr] = expf(pv.z - rm);
        Ps[lc+3][lr] = expf(pv.w - rm);
        *(float4*)&Vs[vr][vc] = *(const float4*)(V + (size_t)(k0 + vr)*QKVLD + vc);
        __syncthreads();
        #pragma unroll
        for (int kk = 0; kk < 16; kk++) {
            float4 ra = *(const float4*)&Ps[kk][ty << 2], rb = *(const float4*)&Vs[kk][tx << 2];
            float ar[4] = {ra.x,ra.y,ra.z,ra.w}, br[4] = {rb.x,rb.y,rb.z,rb.w};
            #pragma unroll
            for (int i = 0; i < 4; i++)
                #pragma unroll
                for (int j = 0; j < 4; j++) acc[i][j] += ar[i]*br[j];
        }
        __syncthreads();
    }
    #pragma unroll
    for (int i = 0; i < 4; i++) {
        int qrow = (ty << 2) + i;
        float inv = rowinv[qrow];
        #pragma unroll
        for (int j = 0; j < 4; j++) {
            size_t idx = (size_t)(b*SS + q0 + qrow)*DD + h*DHH + (tx << 2) + j;
            __nv_bfloat16 hh, ll; split_hl(acc[i][j]*inv, hh, ll);
            oh[idx] = hh; ol[idx] = ll;
        }
    }
}

// ---------------- residual add + LayerNorm (+hi/lo) ----------------
__global__ void __launch_bounds__(256)
add_ln(const float* __restrict__ x1, const float* __restrict__ x2,
       const float* __restrict__ g, const float* __restrict__ bb,
       float* __restrict__ y, __nv_bfloat16* __restrict__ yh, __nv_bfloat16* __restrict__ yl)
{
    __shared__ float red[256];
    const int row = blockIdx.x, t = threadIdx.x;
    const size_t base = (size_t)row*DD;
    float a = x1[base+t] + x2[base+t];
    float c = x1[base+t+256] + x2[base+t+256];
    red[t] = a + c; __syncthreads();
    for (int o = 128; o > 0; o >>= 1) { if (t < o) red[t] += red[t+o]; __syncthreads(); }
    float mu = red[0]*(1.0f/DD); __syncthreads();
    float da = a - mu, dc = c - mu;
    red[t] = da*da + dc*dc; __syncthreads();
    for (int o = 128; o > 0; o >>= 1) { if (t < o) red[t] += red[t+o]; __syncthreads(); }
    float inv = rsqrtf(red[0]*(1.0f/DD) + 1e-6f);
    float v0 = da*inv*g[t] + bb[t], v1 = dc*inv*g[t+256] + bb[t+256];
    y[base+t] = v0; y[base+t+256] = v1;
    __nv_bfloat16 hh, ll;
    split_hl(v0, hh, ll); yh[base+t] = hh;     yl[base+t] = ll;
    split_hl(v1, hh, ll); yh[base+t+256] = hh; yl[base+t+256] = ll;
}

// ---------------- launch ----------------
extern "C" void kernel_launch(void* const* d_in, const int* in_sizes, int n_in,
                              void* d_out, int out_size)
{
    const int*   tokens = (const int*)d_in[0];
    const float* en_out = (const float*)d_in[1];
    const float* en_pad = (const float*)d_in[2];
    const float* emb    = (const float*)d_in[3];
    const float* sa_w = (const float*)d_in[4],  *sa_b = (const float*)d_in[5];
    const float* ca_w = (const float*)d_in[6],  *ca_b = (const float*)d_in[7];
    const float* ff_w1 = (const float*)d_in[8], *ff_b1 = (const float*)d_in[9];
    const float* ff_w2 = (const float*)d_in[10],*ff_b2 = (const float*)d_in[11];
    const float* ln_g = (const float*)d_in[12], *ln_b = (const float*)d_in[13];
    const float* out_w = (const float*)d_in[14],*out_b = (const float*)d_in[15];
    float* out = (float*)d_out;

    float *x,*h,*a,*qkv,*sc,*pr,*dp;
    cudaGetSymbolAddress((void**)&x,g_x); cudaGetSymbolAddress((void**)&h,g_h);
    cudaGetSymbolAddress((void**)&a,g_a); cudaGetSymbolAddress((void**)&qkv,g_qkv);
    cudaGetSymbolAddress((void**)&sc,g_sc); cudaGetSymbolAddress((void**)&pr,g_pr);
    cudaGetSymbolAddress((void**)&dp,g_dp);
    __nv_bfloat16 *wsah,*wsal,*wcah,*wcal,*wf1h,*wf1l,*wf2h,*wf2l,*woh,*wol,*enh,*enl;
    __nv_bfloat16 *xh,*xl,*hh,*hl,*ah,*al,*aoh,*aol,*ffh,*ffl;
    cudaGetSymbolAddress((void**)&wsah,g_wsa_h); cudaGetSymbolAddress((void**)&wsal,g_wsa_l);
    cudaGetSymbolAddress((void**)&wcah,g_wca_h); cudaGetSymbolAddress((void**)&wcal,g_wca_l);
    cudaGetSymbolAddress((void**)&wf1h,g_wf1_h); cudaGetSymbolAddress((void**)&wf1l,g_wf1_l);
    cudaGetSymbolAddress((void**)&wf2h,g_wf2_h); cudaGetSymbolAddress((void**)&wf2l,g_wf2_l);
    cudaGetSymbolAddress((void**)&woh,g_wo_h);   cudaGetSymbolAddress((void**)&wol,g_wo_l);
    cudaGetSymbolAddress((void**)&enh,g_en_h);   cudaGetSymbolAddress((void**)&enl,g_en_l);
    cudaGetSymbolAddress((void**)&xh,g_xh);   cudaGetSymbolAddress((void**)&xl,g_xl);
    cudaGetSymbolAddress((void**)&hh,g_hh);   cudaGetSymbolAddress((void**)&hl,g_hl2);
    cudaGetSymbolAddress((void**)&ah,g_ah);   cudaGetSymbolAddress((void**)&al,g_al);
    cudaGetSymbolAddress((void**)&aoh,g_aoh); cudaGetSymbolAddress((void**)&aol,g_aol);
    cudaGetSymbolAddress((void**)&ffh,g_ffh); cudaGetSymbolAddress((void**)&ffl,g_ffl);

    cudaFuncSetAttribute(tgemm<0,0>, cudaFuncAttributeMaxDynamicSharedMemorySize, TG_DSMEM);
    cudaFuncSetAttribute(tgemm<1,1>, cudaFuncAttributeMaxDynamicSharedMemorySize, TG_DSMEM);

    cvt_hl<<<NW_SA/4/256, 256>>>(sa_w, wsah, wsal, NW_SA/4);
    cvt_hl<<<NW_SA/4/256, 256>>>(ca_w, wcah, wcal, NW_SA/4);
    cvt_hl<<<NW_F1/4/256, 256>>>(ff_w1, wf1h, wf1l, NW_F1/4);
    cvt_hl<<<NW_F1/4/256, 256>>>(ff_w2, wf2h, wf2l, NW_F1/4);
    cvt_hl<<<NW_OUT/4/256, 256>>>(out_w, woh, wol, NW_OUT/4);
    cvt_hl<<<MM*DD/4/256, 256>>>(en_out, enh, enl, MM*DD/4);

    embed_kernel<<<MM, 256>>>(tokens, emb, x, xh, xl, dp);

    const dim3 gS(SS/64, SS/64, BB*HH), gV(1, SS/64, BB*HH);
    for (int i = 0; i < LL; i++) {
        const size_t w4 = (size_t)i*4*DD*DD, b4 = (size_t)i*4*DD;
        // self attention
        tgemm<0,0><<<dim3(QKVLD/128, MM/128), 256, TG_DSMEM>>>(
            xh, xl, wsah+w4, wsal+w4, sa_b+b4, qkv, 0, 0, DD, QKVLD);
        attn_scores<1><<<gS, 256>>>(qkv, dp, sc);
        attn_av_sm<<<gV, 256>>>(sc, qkv, aoh, aol);
        tgemm<0,0><<<dim3(DD/128, MM/128), 256, TG_DSMEM>>>(
            aoh, aol, wsah+w4+3*DD*DD, wsal+w4+3*DD*DD, sa_b+b4+3*DD, pr, 0, 0, DD, DD);
        add_ln<<<MM, 256>>>(x, pr, ln_g+(size_t)(i*3+0)*DD, ln_b+(size_t)(i*3+0)*DD, h, hh, hl);
        // cross attention
        tgemm<0,0><<<dim3(DD/128, MM/128), 256, TG_DSMEM>>>(
            hh, hl, wcah+w4, wcal+w4, ca_b+b4, qkv, 0, 0, DD, QKVLD);
        tgemm<0,0><<<dim3(2*DD/128, MM/128), 256, TG_DSMEM>>>(
            enh, enl, wcah+w4+DD*DD, wcal+w4+DD*DD, ca_b+b4+DD, qkv+DD, 0, 0, DD, QKVLD);
        attn_scores<0><<<gS, 256>>>(qkv, en_pad, sc);
        attn_av_sm<<<gV, 256>>>(sc, qkv, aoh, aol);
        tgemm<0,0><<<dim3(DD/128, MM/128), 256, TG_DSMEM>>>(
            aoh, aol, wcah+w4+3*DD*DD, wcal+w4+3*DD*DD, ca_b+b4+3*DD, pr, 0, 0, DD, DD);
        add_ln<<<MM, 256>>>(h, pr, ln_g+(size_t)(i*3+1)*DD, ln_b+(size_t)(i*3+1)*DD, a, ah, al);
        // feed forward
        tgemm<1,1><<<dim3(FFD/128, MM/128), 256, TG_DSMEM>>>(
            ah, al, wf1h+(size_t)i*FFD*DD, wf1l+(size_t)i*FFD*DD, ff_b1+(size_t)i*FFD,
            0, ffh, ffl, DD, FFD);
        tgemm<0,0><<<dim3(DD/128, MM/128), 256, TG_DSMEM>>>(
            ffh, ffl, wf2h+(size_t)i*FFD*DD, wf2l+(size_t)i*FFD*DD, ff_b2+(size_t)i*DD,
            pr, 0, 0, FFD, DD);
        add_ln<<<MM, 256>>>(a, pr, ln_g+(size_t)(i*3+2)*DD, ln_b+(size_t)(i*3+2)*DD, x, xh, xl);
    }
    tgemm<0,0><<<dim3(VV/128, MM/128), 256, TG_DSMEM>>>(
        xh, xl, woh, wol, out_b, out, 0, 0, DD, VV);
}

// round 6
// speedup vs baseline: 1.7675x; 1.0981x over previous
#include <cuda_runtime.h>
#include <cuda_bf16.h>
#include <math.h>
#include <stdint.h>

typedef unsigned int u32; typedef unsigned long long u64;
#define BB 4
#define SS 512
#define DD 512
#define HH 8
#define DHH 64
#define FFD 2048
#define LL 6
#define VV 32000
#define MM (BB*SS)
#define QKVLD (3*DD)

__device__ float g_x[MM*DD], g_h[MM*DD], g_a[MM*DD], g_qkv[MM*3*DD];
__device__ float g_sc[BB*HH*SS*SS], g_pr[MM*DD], g_dp[MM];
#define NW_SA (LL*4*DD*DD)
#define NW_F1 (LL*FFD*DD)
#define NW_OUT (VV*DD)
__device__ __nv_bfloat16 g_wsa_h[NW_SA], g_wsa_l[NW_SA], g_wca_h[NW_SA], g_wca_l[NW_SA];
__device__ __nv_bfloat16 g_wf1_h[NW_F1], g_wf1_l[NW_F1], g_wf2_h[NW_F1], g_wf2_l[NW_F1];
__device__ __nv_bfloat16 g_wo_h[NW_OUT], g_wo_l[NW_OUT], g_en_h[MM*DD], g_en_l[MM*DD];
__device__ __nv_bfloat16 g_xh[MM*DD], g_xl[MM*DD], g_hh[MM*DD], g_hl2[MM*DD];
__device__ __nv_bfloat16 g_ah[MM*DD], g_al[MM*DD], g_aoh[MM*DD], g_aol[MM*DD];
__device__ __nv_bfloat16 g_ffh[MM*FFD], g_ffl[MM*FFD];

__device__ __forceinline__ u32 smem_u32(const void* p) {
    u32 a; asm("{ .reg .u64 t; cvta.to.shared.u64 t, %1; cvt.u32.u64 %0, t; }" : "=r"(a) : "l"(p)); return a;
}
__device__ __forceinline__ void ldsm4(u32& r0, u32& r1, u32& r2, u32& r3, u32 addr) {
    asm volatile("ldmatrix.sync.aligned.m8n8.x4.shared.b16 {%0,%1,%2,%3}, [%4];"
                 : "=r"(r0), "=r"(r1), "=r"(r2), "=r"(r3) : "r"(addr));
}
__device__ __forceinline__ void mma16816(float* d, const u32* a, const u32* b) {
    asm volatile("mma.sync.aligned.m16n8k16.row.col.f32.bf16.bf16.f32 "
                 "{%0,%1,%2,%3}, {%4,%5,%6,%7}, {%8,%9}, {%0,%1,%2,%3};"
                 : "+f"(d[0]), "+f"(d[1]), "+f"(d[2]), "+f"(d[3])
                 : "r"(a[0]), "r"(a[1]), "r"(a[2]), "r"(a[3]), "r"(b[0]), "r"(b[1]));
}
__device__ __forceinline__ void cpa16(u32 saddr, const void* gaddr) {
    asm volatile("cp.async.cg.shared.global [%0], [%1], 16;" :: "r"(saddr), "l"(gaddr));
}
__device__ __forceinline__ void cpa_commit() { asm volatile("cp.async.commit_group;"); }
__device__ __forceinline__ void cpa_wait1()  { asm volatile("cp.async.wait_group 1;"); }
__device__ __forceinline__ void split_hl(float v, __nv_bfloat16& h, __nv_bfloat16& l) {
    h = __float2bfloat16(v); l = __float2bfloat16(v - __bfloat162float(h));
}

__global__ void cvt_hl(const float* __restrict__ s, __nv_bfloat16* __restrict__ hi,
                       __nv_bfloat16* __restrict__ lo, int n4) {
    int i = blockIdx.x*blockDim.x + threadIdx.x;
    if (i >= n4) return;
    float4 v = ((const float4*)s)[i];
    __nv_bfloat16 h, l;
    split_hl(v.x,h,l); hi[i*4+0]=h; lo[i*4+0]=l;
    split_hl(v.y,h,l); hi[i*4+1]=h; lo[i*4+1]=l;
    split_hl(v.z,h,l); hi[i*4+2]=h; lo[i*4+2]=l;
    split_hl(v.w,h,l); hi[i*4+3]=h; lo[i*4+3]=l;
}

// ======== HMMA split-3 GEMM, cp.async 3-stage, BK=64, M-tile templated =======
// C[M,N] = (Ah+Al)(Wh+Wl)^T + bias ≈ Ah·Wh + Ah·Wl + Al·Wh   (fp32 accum)
#define BK 64
#define SPITCH 72
#define TG_STAGES 3
#define WTILEE (128*SPITCH)
template<int RELU, int OUTHL, int MT>
__global__ void __launch_bounds__(256)
tgemm(const __nv_bfloat16* __restrict__ Ah, const __nv_bfloat16* __restrict__ Al,
      const __nv_bfloat16* __restrict__ Wh, const __nv_bfloat16* __restrict__ Wl,
      const float* __restrict__ bias, float* __restrict__ C,
      __nv_bfloat16* __restrict__ Ch, __nv_bfloat16* __restrict__ Cl, int K, int ldc)
{
    constexpr int ATILEE = MT*SPITCH;                  // elems per A tile
    constexpr int STAGEE = ATILEE + WTILEE;            // elems per stage
    constexpr int WM = MT/32;                          // mma m-tiles per warp
    extern __shared__ __align__(16) __nv_bfloat16 sm[];
    const int t = threadIdx.x, lane = t & 31, wid = t >> 5;
    const int m0 = blockIdx.y*MT, n0 = blockIdx.x*128;
    const int wm = wid >> 2, wn = wid & 3;
    const int mbase = wm*(MT/2), nbase = wn*32;
    const int mat = lane >> 3, rowin = lane & 7;
    const int a_row = (mat & 1)*8 + rowin, a_col = (mat >> 1)*8;
    const int b_row = (mat >> 1)*8 + rowin, b_col = (mat & 1)*8;
    // loaders: W tile 128x64 -> 2 thr/row, 4x16B each; A: MT rows
    const int wlrow = t >> 1, wlcol = (t & 1)*32;
    const int alrow = (MT == 128) ? (t >> 1) : (t >> 2);
    const int alcol = (MT == 128) ? ((t & 1)*32) : ((t & 3)*16);
    const int kc = K/BK, nch = 3*kc;

    const u32 sbase = smem_u32(&sm[0]);

    float acc[WM][4][4];
    #pragma unroll
    for (int i = 0; i < WM; i++)
        #pragma unroll
        for (int j = 0; j < 4; j++)
            #pragma unroll
            for (int q = 0; q < 4; q++) acc[i][j][q] = 0.f;

    auto issue = [&](int c) {
        const int s = c % TG_STAGES;
        const int seg = c / kc, kq = (c - seg*kc)*BK;
        const __nv_bfloat16* as = ((seg == 2) ? Al : Ah) + (size_t)(m0+alrow)*K + kq + alcol;
        const __nv_bfloat16* ws = ((seg == 1) ? Wl : Wh) + (size_t)(n0+wlrow)*K + kq + wlcol;
        const u32 da = sbase + (u32)((s*STAGEE + alrow*SPITCH + alcol)*2);
        const u32 dw = sbase + (u32)((s*STAGEE + ATILEE + wlrow*SPITCH + wlcol)*2);
        if (MT == 128) {
            cpa16(da, as); cpa16(da+16, as+8); cpa16(da+32, as+16); cpa16(da+48, as+24);
        } else {
            cpa16(da, as); cpa16(da+16, as+8);
        }
        cpa16(dw, ws); cpa16(dw+16, ws+8); cpa16(dw+32, ws+16); cpa16(dw+48, ws+24);
    };

    #pragma unroll
    for (int c = 0; c < TG_STAGES-1; c++) { issue(c); cpa_commit(); }

    for (int c = 0; c < nch; ++c) {
        cpa_wait1();
        __syncthreads();
        const int s = c % TG_STAGES;
        const u32 abase = sbase + (u32)(s*STAGEE*2);
        const u32 wbase = abase + (u32)(ATILEE*2);
        #pragma unroll
        for (int ks = 0; ks < BK/16; ks++) {
            u32 af[WM][4], bfr[2][4];
            #pragma unroll
            for (int mi = 0; mi < WM; mi++) {
                u32 ad = abase + (u32)(((mbase + mi*16 + a_row)*SPITCH + ks*16 + a_col)*2);
                ldsm4(af[mi][0], af[mi][1], af[mi][2], af[mi][3], ad);
            }
            #pragma unroll
            for (int g = 0; g < 2; g++) {
                u32 bd = wbase + (u32)(((nbase + g*16 + b_row)*SPITCH + ks*16 + b_col)*2);
                ldsm4(bfr[g][0], bfr[g][1], bfr[g][2], bfr[g][3], bd);
            }
            #pragma unroll
            for (int mi = 0; mi < WM; mi++)
                #pragma unroll
                for (int ni = 0; ni < 4; ni++)
                    mma16816(acc[mi][ni], af[mi], &bfr[ni >> 1][(ni & 1)*2]);
        }
        const int cn = c + TG_STAGES - 1;
        if (cn < nch) issue(cn);
        cpa_commit();
    }

    const int r = lane >> 2, c2 = (lane & 3) << 1;
    #pragma unroll
    for (int mi = 0; mi < WM; mi++) {
        #pragma unroll
        for (int ni = 0; ni < 4; ni++) {
            const int m = m0 + mbase + mi*16 + r;
            const int n = n0 + nbase + ni*8 + c2;
            float b0 = bias[n], b1 = bias[n+1];
            float v0 = acc[mi][ni][0] + b0, v1 = acc[mi][ni][1] + b1;
            float v2 = acc[mi][ni][2] + b0, v3 = acc[mi][ni][3] + b1;
            if (RELU) { v0=fmaxf(v0,0.f); v1=fmaxf(v1,0.f); v2=fmaxf(v2,0.f); v3=fmaxf(v3,0.f); }
            if (OUTHL) {
                __nv_bfloat16 h, l;
                size_t i0 = (size_t)m*ldc + n, i1 = (size_t)(m+8)*ldc + n;
                split_hl(v0,h,l); Ch[i0]=h;   Cl[i0]=l;
                split_hl(v1,h,l); Ch[i0+1]=h; Cl[i0+1]=l;
                split_hl(v2,h,l); Ch[i1]=h;   Cl[i1]=l;
                split_hl(v3,h,l); Ch[i1+1]=h; Cl[i1+1]=l;
            } else {
                *(float2*)(C + (size_t)m*ldc + n)     = make_float2(v0, v1);
                *(float2*)(C + (size_t)(m+8)*ldc + n) = make_float2(v2, v3);
            }
        }
    }
}
#define DSM(MT) (TG_STAGES*((MT)+128)*SPITCH*2)

// ---------------- embedding ----------------
__global__ void embed_kernel(const int* __restrict__ tokens, const float* __restrict__ emb,
                             float* __restrict__ x, __nv_bfloat16* __restrict__ xh,
                             __nv_bfloat16* __restrict__ xl, float* __restrict__ depad)
{
    int row = blockIdx.x, s = row & (SS-1), tok = tokens[row];
    if (threadIdx.x == 0) depad[row] = (tok == 0) ? 1.0f : 0.0f;
    const float sq = sqrtf((float)DD);
    for (int d = threadIdx.x; d < DD; d += blockDim.x) {
        float i = (float)((d >> 1) << 1)/(float)DD;
        float em = (float)s*powf(10000.0f, -i);
        float pe = ((d & 1) == 0) ? sinf(em) : cosf(em);
        float v = emb[(size_t)tok*DD + d]*sq + pe;
        x[(size_t)row*DD + d] = v;
        __nv_bfloat16 h, l; split_hl(v, h, l);
        xh[(size_t)row*DD + d] = h; xl[(size_t)row*DD + d] = l;
    }
}

// ---------------- attention scores ----------------
template<int CAUSAL>
__global__ void __launch_bounds__(256)
attn_scores(const float* __restrict__ qkv, const float* __restrict__ mask, float* __restrict__ scores)
{
    __shared__ float Qs[16][64], Ks[16][64];
    const int z = blockIdx.z, b = z >> 3, h = z & 7;
    const int q0 = blockIdx.y*64, k0v = blockIdx.x*64;
    const int t = threadIdx.x, lr = t >> 2, lc = (t & 3) << 2, tx = t & 15, ty = t >> 4;
    const float* Q  = qkv + (size_t)(b*SS + q0 + lr)*QKVLD + h*DHH + lc;
    const float* Kv = qkv + (size_t)(b*SS + k0v + lr)*QKVLD + DD + h*DHH + lc;
    float acc[4][4] = {};
    for (int k0 = 0; k0 < DHH; k0 += 16) {
        float4 av = *(const float4*)(Q + k0), wv = *(const float4*)(Kv + k0);
        Qs[lc+0][lr]=av.x; Qs[lc+1][lr]=av.y; Qs[lc+2][lr]=av.z; Qs[lc+3][lr]=av.w;
        Ks[lc+0][lr]=wv.x; Ks[lc+1][lr]=wv.y; Ks[lc+2][lr]=wv.z; Ks[lc+3][lr]=wv.w;
        __syncthreads();
        #pragma unroll
        for (int kk = 0; kk < 16; kk++) {
            float4 ra = *(const float4*)&Qs[kk][ty << 2], rb = *(const float4*)&Ks[kk][tx << 2];
            float ar[4] = {ra.x,ra.y,ra.z,ra.w}, br[4] = {rb.x,rb.y,rb.z,rb.w};
            #pragma unroll
            for (int i = 0; i < 4; i++)
                #pragma unroll
                for (int j = 0; j < 4; j++) acc[i][j] += ar[i]*br[j];
        }
        __syncthreads();
    }
    #pragma unroll
    for (int i = 0; i < 4; i++) {
        int qq = q0 + (ty << 2) + i;
        #pragma unroll
        for (int j = 0; j < 4; j++) {
            int kq = k0v + (tx << 2) + j;
            float mv = mask[b*SS + kq];
            if (CAUSAL && kq > qq) mv = 1.0f;
            scores[((size_t)z*SS + qq)*SS + kq] = acc[i][j]*0.125f - mv*1e6f;
        }
    }
}

// ------- attn AV with fused softmax (bf16 hi/lo out) ------------------------
__global__ void __launch_bounds__(256)
attn_av_sm(const float* __restrict__ S, const float* __restrict__ qkv,
           __nv_bfloat16* __restrict__ oh, __nv_bfloat16* __restrict__ ol)
{
    __shared__ float Ps[16][64], Vs[16][64];
    __shared__ float rowm[64], rowinv[64];
    __shared__ float pm[64][4], psum[64][4];
    const int z = blockIdx.z, b = z >> 3, h = z & 7;
    const int q0 = blockIdx.y*64;
    const int t = threadIdx.x;
    {
        int r = t >> 2, cseg = (t & 3)*128;
        const float* p = S + ((size_t)z*SS + q0 + r)*SS + cseg;
        float m = -1e30f, s = 0.f;
        #pragma unroll 4
        for (int i = 0; i < 128; i += 4) {
            float4 v = *(const float4*)(p + i);
            float mx = fmaxf(fmaxf(v.x, v.y), fmaxf(v.z, v.w));
            if (mx > m) { s *= expf(m - mx); m = mx; }
            s += expf(v.x-m) + expf(v.y-m) + expf(v.z-m) + expf(v.w-m);
        }
        pm[r][t & 3] = m; psum[r][t & 3] = s;
    }
    __syncthreads();
    if (t < 64) {
        float m0 = pm[t][0], m1 = pm[t][1], m2 = pm[t][2], m3 = pm[t][3];
        float M = fmaxf(fmaxf(m0, m1), fmaxf(m2, m3));
        float sm = psum[t][0]*expf(m0-M) + psum[t][1]*expf(m1-M)
                 + psum[t][2]*expf(m2-M) + psum[t][3]*expf(m3-M);
        rowm[t] = M; rowinv[t] = 1.0f/sm;
    }
    __syncthreads();
    const int lr = t >> 2, lc = (t & 3) << 2;
    const int vr = t >> 4, vc = (t & 15) << 2, tx = t & 15, ty = t >> 4;
    const float* P = S + ((size_t)z*SS + q0)*SS;
    const float* V = qkv + (size_t)(b*SS)*QKVLD + 2*DD + h*DHH;
    const float rm = rowm[lr];
    float acc[4][4] = {};
    for (int k0 = 0; k0 < SS; k0 += 16) {
        float4 pv = *(const float4*)(P + (size_t)lr*SS + k0 + lc);
        Ps[lc+0][lr] = expf(pv.x - rm);
        Ps[lc+1][lr] = expf(pv.y - rm);
        Ps[lc+2][lr] = expf(pv.z - rm);
        Ps[lc+3][lr] = expf(pv.w - rm);
        *(float4*)&Vs[vr][vc] = *(const float4*)(V + (size_t)(k0 + vr)*QKVLD + vc);
        __syncthreads();
        #pragma unroll
        for (int kk = 0; kk < 16; kk++) {
            float4 ra = *(const float4*)&Ps[kk][ty << 2], rb = *(const float4*)&Vs[kk][tx << 2];
            float ar[4] = {ra.x,ra.y,ra.z,ra.w}, br[4] = {rb.x,rb.y,rb.z,rb.w};
            #pragma unroll
            for (int i = 0; i < 4; i++)
                #pragma unroll
                for (int j = 0; j < 4; j++) acc[i][j] += ar[i]*br[j];
        }
        __syncthreads();
    }
    #pragma unroll
    for (int i = 0; i < 4; i++) {
        int qrow = (ty << 2) + i;
        float inv = rowinv[qrow];
        #pragma unroll
        for (int j = 0; j < 4; j++) {
            size_t idx = (size_t)(b*SS + q0 + qrow)*DD + h*DHH + (tx << 2) + j;
            __nv_bfloat16 hh, ll; split_hl(acc[i][j]*inv, hh, ll);
            oh[idx] = hh; ol[idx] = ll;
        }
    }
}

// ---------------- residual add + LayerNorm (+hi/lo) ----------------
__global__ void __launch_bounds__(256)
add_ln(const float* __restrict__ x1, const float* __restrict__ x2,
       const float* __restrict__ g, const float* __restrict__ bb,
       float* __restrict__ y, __nv_bfloat16* __restrict__ yh, __nv_bfloat16* __restrict__ yl)
{
    __shared__ float red[256];
    const int row = blockIdx.x, t = threadIdx.x;
    const size_t base = (size_t)row*DD;
    float a = x1[base+t] + x2[base+t];
    float c = x1[base+t+256] + x2[base+t+256];
    red[t] = a + c; __syncthreads();
    for (int o = 128; o > 0; o >>= 1) { if (t < o) red[t] += red[t+o]; __syncthreads(); }
    float mu = red[0]*(1.0f/DD); __syncthreads();
    float da = a - mu, dc = c - mu;
    red[t] = da*da + dc*dc; __syncthreads();
    for (int o = 128; o > 0; o >>= 1) { if (t < o) red[t] += red[t+o]; __syncthreads(); }
    float inv = rsqrtf(red[0]*(1.0f/DD) + 1e-6f);
    float v0 = da*inv*g[t] + bb[t], v1 = dc*inv*g[t+256] + bb[t+256];
    y[base+t] = v0; y[base+t+256] = v1;
    __nv_bfloat16 hh, ll;
    split_hl(v0, hh, ll); yh[base+t] = hh;     yl[base+t] = ll;
    split_hl(v1, hh, ll); yh[base+t+256] = hh; yl[base+t+256] = ll;
}

// ---------------- launch ----------------
extern "C" void kernel_launch(void* const* d_in, const int* in_sizes, int n_in,
                              void* d_out, int out_size)
{
    const int*   tokens = (const int*)d_in[0];
    const float* en_out = (const float*)d_in[1];
    const float* en_pad = (const float*)d_in[2];
    const float* emb    = (const float*)d_in[3];
    const float* sa_w = (const float*)d_in[4],  *sa_b = (const float*)d_in[5];
    const float* ca_w = (const float*)d_in[6],  *ca_b = (const float*)d_in[7];
    const float* ff_w1 = (const float*)d_in[8], *ff_b1 = (const float*)d_in[9];
    const float* ff_w2 = (const float*)d_in[10],*ff_b2 = (const float*)d_in[11];
    const float* ln_g = (const float*)d_in[12], *ln_b = (const float*)d_in[13];
    const float* out_w = (const float*)d_in[14],*out_b = (const float*)d_in[15];
    float* out = (float*)d_out;

    float *x,*h,*a,*qkv,*sc,*pr,*dp;
    cudaGetSymbolAddress((void**)&x,g_x); cudaGetSymbolAddress((void**)&h,g_h);
    cudaGetSymbolAddress((void**)&a,g_a); cudaGetSymbolAddress((void**)&qkv,g_qkv);
    cudaGetSymbolAddress((void**)&sc,g_sc); cudaGetSymbolAddress((void**)&pr,g_pr);
    cudaGetSymbolAddress((void**)&dp,g_dp);
    __nv_bfloat16 *wsah,*wsal,*wcah,*wcal,*wf1h,*wf1l,*wf2h,*wf2l,*woh,*wol,*enh,*enl;
    __nv_bfloat16 *xh,*xl,*hh,*hl,*ah,*al,*aoh,*aol,*ffh,*ffl;
    cudaGetSymbolAddress((void**)&wsah,g_wsa_h); cudaGetSymbolAddress((void**)&wsal,g_wsa_l);
    cudaGetSymbolAddress((void**)&wcah,g_wca_h); cudaGetSymbolAddress((void**)&wcal,g_wca_l);
    cudaGetSymbolAddress((void**)&wf1h,g_wf1_h); cudaGetSymbolAddress((void**)&wf1l,g_wf1_l);
    cudaGetSymbolAddress((void**)&wf2h,g_wf2_h); cudaGetSymbolAddress((void**)&wf2l,g_wf2_l);
    cudaGetSymbolAddress((void**)&woh,g_wo_h);   cudaGetSymbolAddress((void**)&wol,g_wo_l);
    cudaGetSymbolAddress((void**)&enh,g_en_h);   cudaGetSymbolAddress((void**)&enl,g_en_l);
    cudaGetSymbolAddress((void**)&xh,g_xh);   cudaGetSymbolAddress((void**)&xl,g_xl);
    cudaGetSymbolAddress((void**)&hh,g_hh);   cudaGetSymbolAddress((void**)&hl,g_hl2);
    cudaGetSymbolAddress((void**)&ah,g_ah);   cudaGetSymbolAddress((void**)&al,g_al);
    cudaGetSymbolAddress((void**)&aoh,g_aoh); cudaGetSymbolAddress((void**)&aol,g_aol);
    cudaGetSymbolAddress((void**)&ffh,g_ffh); cudaGetSymbolAddress((void**)&ffl,g_ffl);

    cudaFuncSetAttribute(tgemm<0,0,128>, cudaFuncAttributeMaxDynamicSharedMemorySize, DSM(128));
    cudaFuncSetAttribute(tgemm<0,0,64>,  cudaFuncAttributeMaxDynamicSharedMemorySize, DSM(64));
    cudaFuncSetAttribute(tgemm<1,1,128>, cudaFuncAttributeMaxDynamicSharedMemorySize, DSM(128));

    cvt_hl<<<NW_SA/4/256, 256>>>(sa_w, wsah, wsal, NW_SA/4);
    cvt_hl<<<NW_SA/4/256, 256>>>(ca_w, wcah, wcal, NW_SA/4);
    cvt_hl<<<NW_F1/4/256, 256>>>(ff_w1, wf1h, wf1l, NW_F1/4);
    cvt_hl<<<NW_F1/4/256, 256>>>(ff_w2, wf2h, wf2l, NW_F1/4);
    cvt_hl<<<NW_OUT/4/256, 256>>>(out_w, woh, wol, NW_OUT/4);
    cvt_hl<<<MM*DD/4/256, 256>>>(en_out, enh, enl, MM*DD/4);

    embed_kernel<<<MM, 256>>>(tokens, emb, x, xh, xl, dp);

    const dim3 gS(SS/64, SS/64, BB*HH), gV(1, SS/64, BB*HH);
    for (int i = 0; i < LL; i++) {
        const size_t w4 = (size_t)i*4*DD*DD, b4 = (size_t)i*4*DD;
        // self attention
        tgemm<0,0,128><<<dim3(QKVLD/128, MM/128), 256, DSM(128)>>>(
            xh, xl, wsah+w4, wsal+w4, sa_b+b4, qkv, 0, 0, DD, QKVLD);
        attn_scores<1><<<gS, 256>>>(qkv, dp, sc);
        attn_av_sm<<<gV, 256>>>(sc, qkv, aoh, aol);
        tgemm<0,0,64><<<dim3(DD/128, MM/64), 256, DSM(64)>>>(
            aoh, aol, wsah+w4+3*DD*DD, wsal+w4+3*DD*DD, sa_b+b4+3*DD, pr, 0, 0, DD, DD);
        add_ln<<<MM, 256>>>(x, pr, ln_g+(size_t)(i*3+0)*DD, ln_b+(size_t)(i*3+0)*DD, h, hh, hl);
        // cross attention
        tgemm<0,0,64><<<dim3(DD/128, MM/64), 256, DSM(64)>>>(
            hh, hl, wcah+w4, wcal+w4, ca_b+b4, qkv, 0, 0, DD, QKVLD);
        tgemm<0,0,128><<<dim3(2*DD/128, MM/128), 256, DSM(128)>>>(
            enh, enl, wcah+w4+DD*DD, wcal+w4+DD*DD, ca_b+b4+DD, qkv+DD, 0, 0, DD, QKVLD);
        attn_scores<0><<<gS, 256>>>(qkv, en_pad, sc);
        attn_av_sm<<<gV, 256>>>(sc, qkv, aoh, aol);
        tgemm<0,0,64><<<dim3(DD/128, MM/64), 256, DSM(64)>>>(
            aoh, aol, wcah+w4+3*DD*DD, wcal+w4+3*DD*DD, ca_b+b4+3*DD, pr, 0, 0, DD, DD);
        add_ln<<<MM, 256>>>(h, pr, ln_g+(size_t)(i*3+1)*DD, ln_b+(size_t)(i*3+1)*DD, a, ah, al);
        // feed forward
        tgemm<1,1,128><<<dim3(FFD/128, MM/128), 256, DSM(128)>>>(
            ah, al, wf1h+(size_t)i*FFD*DD, wf1l+(size_t)i*FFD*DD, ff_b1+(size_t)i*FFD,
            0, ffh, ffl, DD, FFD);
        tgemm<0,0,64><<<dim3(DD/128, MM/64), 256, DSM(64)>>>(
            ffh, ffl, wf2h+(size_t)i*FFD*DD, wf2l+(size_t)i*FFD*DD, ff_b2+(size_t)i*DD,
            pr, 0, 0, FFD, DD);
        add_ln<<<MM, 256>>>(a, pr, ln_g+(size_t)(i*3+2)*DD, ln_b+(size_t)(i*3+2)*DD, x, xh, xl);
    }
    tgemm<0,0,128><<<dim3(VV/128, MM/128), 256, DSM(128)>>>(
        xh, xl, woh, wol, out_b, out, 0, 0, DD, VV);
}

// round 8
// speedup vs baseline: 1.9699x; 1.1145x over previous
#include <cuda_runtime.h>
#include <cuda_bf16.h>
#include <math.h>
#include <stdint.h>

typedef unsigned int u32; typedef unsigned long long u64;
#define BB 4
#define SS 512
#define DD 512
#define HH 8
#define DHH 64
#define FFD 2048
#define LL 6
#define VV 32000
#define MM (BB*SS)
#define QKVLD (3*DD)

__device__ float g_x[MM*DD], g_h[MM*DD], g_a[MM*DD], g_qkv[MM*3*DD];
__device__ float g_sc[BB*HH*SS*SS], g_pr[MM*DD], g_dp[MM];
#define NW_SA (LL*4*DD*DD)
#define NW_F1 (LL*FFD*DD)
#define NW_OUT (VV*DD)
__device__ __nv_bfloat16 g_wsa_h[NW_SA], g_wsa_l[NW_SA], g_wca_h[NW_SA], g_wca_l[NW_SA];
__device__ __nv_bfloat16 g_wf1_h[NW_F1], g_wf1_l[NW_F1], g_wf2_h[NW_F1], g_wf2_l[NW_F1];
__device__ __nv_bfloat16 g_wo_h[NW_OUT], g_wo_l[NW_OUT], g_en_h[MM*DD], g_en_l[MM*DD];
__device__ __nv_bfloat16 g_xh[MM*DD], g_xl[MM*DD], g_hh[MM*DD], g_hl2[MM*DD];
__device__ __nv_bfloat16 g_ah[MM*DD], g_al[MM*DD], g_aoh[MM*DD], g_aol[MM*DD];
__device__ __nv_bfloat16 g_ffh[MM*FFD], g_ffl[MM*FFD];

__device__ __forceinline__ u32 smem_u32(const void* p) {
    u32 a; asm("{ .reg .u64 t; cvta.to.shared.u64 t, %1; cvt.u32.u64 %0, t; }" : "=r"(a) : "l"(p)); return a;
}
__device__ __forceinline__ void ldsm4(u32& r0, u32& r1, u32& r2, u32& r3, u32 addr) {
    asm volatile("ldmatrix.sync.aligned.m8n8.x4.shared.b16 {%0,%1,%2,%3}, [%4];"
                 : "=r"(r0), "=r"(r1), "=r"(r2), "=r"(r3) : "r"(addr));
}
__device__ __forceinline__ void mma16816(float* d, const u32* a, const u32* b) {
    asm volatile("mma.sync.aligned.m16n8k16.row.col.f32.bf16.bf16.f32 "
                 "{%0,%1,%2,%3}, {%4,%5,%6,%7}, {%8,%9}, {%0,%1,%2,%3};"
                 : "+f"(d[0]), "+f"(d[1]), "+f"(d[2]), "+f"(d[3])
                 : "r"(a[0]), "r"(a[1]), "r"(a[2]), "r"(a[3]), "r"(b[0]), "r"(b[1]));
}
__device__ __forceinline__ void cpa16(u32 saddr, const void* gaddr) {
    asm volatile("cp.async.cg.shared.global [%0], [%1], 16;" :: "r"(saddr), "l"(gaddr));
}
__device__ __forceinline__ void cpa_commit() { asm volatile("cp.async.commit_group;"); }
__device__ __forceinline__ void cpa_wait1()  { asm volatile("cp.async.wait_group 1;"); }
__device__ __forceinline__ void split_hl(float v, __nv_bfloat16& h, __nv_bfloat16& l) {
    h = __float2bfloat16(v); l = __float2bfloat16(v - __bfloat162float(h));
}

__global__ void cvt_hl(const float* __restrict__ s, __nv_bfloat16* __restrict__ hi,
                       __nv_bfloat16* __restrict__ lo, int n4) {
    int i = blockIdx.x*blockDim.x + threadIdx.x;
    if (i >= n4) return;
    float4 v = ((const float4*)s)[i];
    __nv_bfloat16 h, l;
    split_hl(v.x,h,l); hi[i*4+0]=h; lo[i*4+0]=l;
    split_hl(v.y,h,l); hi[i*4+1]=h; lo[i*4+1]=l;
    split_hl(v.z,h,l); hi[i*4+2]=h; lo[i*4+2]=l;
    split_hl(v.w,h,l); hi[i*4+3]=h; lo[i*4+3]=l;
}

// ======== HMMA split-3 GEMM, cp.async 3-stage, BK=64, M-tile templated =======
#define BK 64
#define SPITCH 72
#define TG_STAGES 3
#define WTILEE (128*SPITCH)
template<int RELU, int OUTHL, int MT>
__global__ void __launch_bounds__(256)
tgemm(const __nv_bfloat16* __restrict__ Ah, const __nv_bfloat16* __restrict__ Al,
      const __nv_bfloat16* __restrict__ Wh, const __nv_bfloat16* __restrict__ Wl,
      const float* __restrict__ bias, float* __restrict__ C,
      __nv_bfloat16* __restrict__ Ch, __nv_bfloat16* __restrict__ Cl, int K, int ldc)
{
    constexpr int ATILEE = MT*SPITCH;
    constexpr int STAGEE = ATILEE + WTILEE;
    constexpr int WM = MT/32;
    extern __shared__ __align__(16) __nv_bfloat16 sm[];
    const int t = threadIdx.x, lane = t & 31, wid = t >> 5;
    const int m0 = blockIdx.y*MT, n0 = blockIdx.x*128;
    const int wm = wid >> 2, wn = wid & 3;
    const int mbase = wm*(MT/2), nbase = wn*32;
    const int mat = lane >> 3, rowin = lane & 7;
    const int a_row = (mat & 1)*8 + rowin, a_col = (mat >> 1)*8;
    const int b_row = (mat >> 1)*8 + rowin, b_col = (mat & 1)*8;
    const int wlrow = t >> 1, wlcol = (t & 1)*32;
    const int alrow = (MT == 128) ? (t >> 1) : (t >> 2);
    const int alcol = (MT == 128) ? ((t & 1)*32) : ((t & 3)*16);
    const int kc = K/BK, nch = 3*kc;
    const u32 sbase = smem_u32(&sm[0]);

    float acc[WM][4][4];
    #pragma unroll
    for (int i = 0; i < WM; i++)
        #pragma unroll
        for (int j = 0; j < 4; j++)
            #pragma unroll
            for (int q = 0; q < 4; q++) acc[i][j][q] = 0.f;

    auto issue = [&](int c) {
        const int s = c % TG_STAGES;
        const int seg = c / kc, kq = (c - seg*kc)*BK;
        const __nv_bfloat16* as = ((seg == 2) ? Al : Ah) + (size_t)(m0+alrow)*K + kq + alcol;
        const __nv_bfloat16* ws = ((seg == 1) ? Wl : Wh) + (size_t)(n0+wlrow)*K + kq + wlcol;
        const u32 da = sbase + (u32)((s*STAGEE + alrow*SPITCH + alcol)*2);
        const u32 dw = sbase + (u32)((s*STAGEE + ATILEE + wlrow*SPITCH + wlcol)*2);
        if (MT == 128) {
            cpa16(da, as); cpa16(da+16, as+8); cpa16(da+32, as+16); cpa16(da+48, as+24);
        } else {
            cpa16(da, as); cpa16(da+16, as+8);
        }
        cpa16(dw, ws); cpa16(dw+16, ws+8); cpa16(dw+32, ws+16); cpa16(dw+48, ws+24);
    };

    #pragma unroll
    for (int c = 0; c < TG_STAGES-1; c++) { issue(c); cpa_commit(); }

    for (int c = 0; c < nch; ++c) {
        cpa_wait1();
        __syncthreads();
        const int s = c % TG_STAGES;
        const u32 abase = sbase + (u32)(s*STAGEE*2);
        const u32 wbase = abase + (u32)(ATILEE*2);
        #pragma unroll
        for (int ks = 0; ks < BK/16; ks++) {
            u32 af[WM][4], bfr[2][4];
            #pragma unroll
            for (int mi = 0; mi < WM; mi++) {
                u32 ad = abase + (u32)(((mbase + mi*16 + a_row)*SPITCH + ks*16 + a_col)*2);
                ldsm4(af[mi][0], af[mi][1], af[mi][2], af[mi][3], ad);
            }
            #pragma unroll
            for (int g = 0; g < 2; g++) {
                u32 bd = wbase + (u32)(((nbase + g*16 + b_row)*SPITCH + ks*16 + b_col)*2);
                ldsm4(bfr[g][0], bfr[g][1], bfr[g][2], bfr[g][3], bd);
            }
            #pragma unroll
            for (int mi = 0; mi < WM; mi++)
                #pragma unroll
                for (int ni = 0; ni < 4; ni++)
                    mma16816(acc[mi][ni], af[mi], &bfr[ni >> 1][(ni & 1)*2]);
        }
        const int cn = c + TG_STAGES - 1;
        if (cn < nch) issue(cn);
        cpa_commit();
    }

    const int r = lane >> 2, c2 = (lane & 3) << 1;
    #pragma unroll
    for (int mi = 0; mi < WM; mi++) {
        #pragma unroll
        for (int ni = 0; ni < 4; ni++) {
            const int m = m0 + mbase + mi*16 + r;
            const int n = n0 + nbase + ni*8 + c2;
            float b0 = bias[n], b1 = bias[n+1];
            float v0 = acc[mi][ni][0] + b0, v1 = acc[mi][ni][1] + b1;
            float v2 = acc[mi][ni][2] + b0, v3 = acc[mi][ni][3] + b1;
            if (RELU) { v0=fmaxf(v0,0.f); v1=fmaxf(v1,0.f); v2=fmaxf(v2,0.f); v3=fmaxf(v3,0.f); }
            if (OUTHL) {
                __nv_bfloat16 h, l;
                size_t i0 = (size_t)m*ldc + n, i1 = (size_t)(m+8)*ldc + n;
                split_hl(v0,h,l); Ch[i0]=h;   Cl[i0]=l;
                split_hl(v1,h,l); Ch[i0+1]=h; Cl[i0+1]=l;
                split_hl(v2,h,l); Ch[i1]=h;   Cl[i1]=l;
                split_hl(v3,h,l); Ch[i1+1]=h; Cl[i1+1]=l;
            } else {
                *(float2*)(C + (size_t)m*ldc + n)     = make_float2(v0, v1);
                *(float2*)(C + (size_t)(m+8)*ldc + n) = make_float2(v2, v3);
            }
        }
    }
}
#define DSM(MT) (TG_STAGES*((MT)+128)*SPITCH*2)

// ======== attention scores via HMMA split-3: s = QK^T/8 - mask*1e6 =========
#define SC_TILE (128*SPITCH)
#define SC_DSMEM (4*SC_TILE*2)
template<int CAUSAL>
__global__ void __launch_bounds__(256)
attn_scores_mma(const float* __restrict__ qkv, const float* __restrict__ mask,
                float* __restrict__ scores)
{
    extern __shared__ __align__(16) __nv_bfloat16 sm[];
    __nv_bfloat16 *Qh = sm, *Ql = sm + SC_TILE, *Kh = sm + 2*SC_TILE, *Kl = sm + 3*SC_TILE;
    const int z = blockIdx.z, b = z >> 3, h = z & 7;
    const int q0 = blockIdx.y*128, k0v = blockIdx.x*128;
    const int t = threadIdx.x, lane = t & 31, wid = t >> 5;

    // load + split Q,K tiles: 128 rows x 64 cols = 2048 float4 each; 8/thread
    #pragma unroll
    for (int i = 0; i < 8; i++) {
        int fi = t + i*256;               // 0..2047
        int row = fi >> 4, col = (fi & 15)*4;
        float4 qv = *(const float4*)(qkv + (size_t)(b*SS + q0 + row)*QKVLD + h*DHH + col);
        float4 kv = *(const float4*)(qkv + (size_t)(b*SS + k0v + row)*QKVLD + DD + h*DHH + col);
        __nv_bfloat16 hh, ll;
        int o = row*SPITCH + col;
        split_hl(qv.x,hh,ll); Qh[o+0]=hh; Ql[o+0]=ll;
        split_hl(qv.y,hh,ll); Qh[o+1]=hh; Ql[o+1]=ll;
        split_hl(qv.z,hh,ll); Qh[o+2]=hh; Ql[o+2]=ll;
        split_hl(qv.w,hh,ll); Qh[o+3]=hh; Ql[o+3]=ll;
        split_hl(kv.x,hh,ll); Kh[o+0]=hh; Kl[o+0]=ll;
        split_hl(kv.y,hh,ll); Kh[o+1]=hh; Kl[o+1]=ll;
        split_hl(kv.z,hh,ll); Kh[o+2]=hh; Kl[o+2]=ll;
        split_hl(kv.w,hh,ll); Kh[o+3]=hh; Kl[o+3]=ll;
    }
    __syncthreads();

    const int wm = wid >> 2, wn = wid & 3;
    const int mbase = wm*64, nbase = wn*32;
    const int mat = lane >> 3, rowin = lane & 7;
    const int a_row = (mat & 1)*8 + rowin, a_col = (mat >> 1)*8;
    const int b_row = (mat >> 1)*8 + rowin, b_col = (mat & 1)*8;
    float acc[4][4][4];
    #pragma unroll
    for (int i = 0; i < 4; i++)
        #pragma unroll
        for (int j = 0; j < 4; j++)
            #pragma unroll
            for (int q = 0; q < 4; q++) acc[i][j][q] = 0.f;

    #pragma unroll
    for (int seg = 0; seg < 3; seg++) {
        const u32 abase = smem_u32((seg == 2) ? Ql : Qh);
        const u32 wbase = smem_u32((seg == 1) ? Kl : Kh);
        #pragma unroll
        for (int ks = 0; ks < 4; ks++) {
            u32 af[4][4], bfr[2][4];
            #pragma unroll
            for (int mi = 0; mi < 4; mi++) {
                u32 ad = abase + (u32)(((mbase + mi*16 + a_row)*SPITCH + ks*16 + a_col)*2);
                ldsm4(af[mi][0], af[mi][1], af[mi][2], af[mi][3], ad);
            }
            #pragma unroll
            for (int g = 0; g < 2; g++) {
                u32 bd = wbase + (u32)(((nbase + g*16 + b_row)*SPITCH + ks*16 + b_col)*2);
                ldsm4(bfr[g][0], bfr[g][1], bfr[g][2], bfr[g][3], bd);
            }
            #pragma unroll
            for (int mi = 0; mi < 4; mi++)
                #pragma unroll
                for (int ni = 0; ni < 4; ni++)
                    mma16816(acc[mi][ni], af[mi], &bfr[ni >> 1][(ni & 1)*2]);
        }
    }

    const int r = lane >> 2, c2 = (lane & 3) << 1;
    #pragma unroll
    for (int mi = 0; mi < 4; mi++) {
        #pragma unroll
        for (int ni = 0; ni < 4; ni++) {
            #pragma unroll
            for (int half = 0; half < 2; half++) {
                const int m = q0 + mbase + mi*16 + r + half*8;
                const int n = k0v + nbase + ni*8 + c2;
                float mv0 = mask[b*SS + n], mv1 = mask[b*SS + n + 1];
                if (CAUSAL && n   > m) mv0 = 1.0f;
                if (CAUSAL && n+1 > m) mv1 = 1.0f;
                float v0 = acc[mi][ni][half*2+0]*0.125f - mv0*1e6f;
                float v1 = acc[mi][ni][half*2+1]*0.125f - mv1*1e6f;
                *(float2*)(scores + ((size_t)z*SS + m)*SS + n) = make_float2(v0, v1);
            }
        }
    }
}

// ---------------- embedding ----------------
__global__ void embed_kernel(const int* __restrict__ tokens, const float* __restrict__ emb,
                             float* __restrict__ x, __nv_bfloat16* __restrict__ xh,
                             __nv_bfloat16* __restrict__ xl, float* __restrict__ depad)
{
    int row = blockIdx.x, s = row & (SS-1), tok = tokens[row];
    if (threadIdx.x == 0) depad[row] = (tok == 0) ? 1.0f : 0.0f;
    const float sq = sqrtf((float)DD);
    for (int d = threadIdx.x; d < DD; d += blockDim.x) {
        float i = (float)((d >> 1) << 1)/(float)DD;
        float em = (float)s*powf(10000.0f, -i);
        float pe = ((d & 1) == 0) ? sinf(em) : cosf(em);
        float v = emb[(size_t)tok*DD + d]*sq + pe;
        x[(size_t)row*DD + d] = v;
        __nv_bfloat16 h, l; split_hl(v, h, l);
        xh[(size_t)row*DD + d] = h; xl[(size_t)row*DD + d] = l;
    }
}

// ------- attn AV, fused softmax, single-exp (bf16 hi/lo out) ----------------
__global__ void __launch_bounds__(256)
attn_av_sm(const float* __restrict__ S, const float* __restrict__ qkv,
           __nv_bfloat16* __restrict__ oh, __nv_bfloat16* __restrict__ ol)
{
    __shared__ float Ps[16][64], Vs[16][64];
    __shared__ float rowm[64], rowinv[64];
    __shared__ float pm[64][4];
    const int z = blockIdx.z, b = z >> 3, h = z & 7;
    const int q0 = blockIdx.y*64;
    const int t = threadIdx.x;

    // pass 1: row max only
    {
        int r = t >> 2, cseg = (t & 3)*128;
        const float* p = S + ((size_t)z*SS + q0 + r)*SS + cseg;
        float m = -1e30f;
        #pragma unroll 4
        for (int i = 0; i < 128; i += 4) {
            float4 v = *(const float4*)(p + i);
            m = fmaxf(m, fmaxf(fmaxf(v.x, v.y), fmaxf(v.z, v.w)));
        }
        pm[r][t & 3] = m;
    }
    __syncthreads();
    if (t < 64)
        rowm[t] = fmaxf(fmaxf(pm[t][0], pm[t][1]), fmaxf(pm[t][2], pm[t][3]));
    __syncthreads();

    // pass 2: single exp; accumulate O_unnorm and row sum together
    const int lr = t >> 2, lc = (t & 3) << 2;
    const int vr = t >> 4, vc = (t & 15) << 2, tx = t & 15, ty = t >> 4;
    const float* P = S + ((size_t)z*SS + q0)*SS;
    const float* V = qkv + (size_t)(b*SS)*QKVLD + 2*DD + h*DHH;
    const float rm = rowm[lr];
    float acc[4][4] = {};
    float psumv = 0.f;
    for (int k0 = 0; k0 < SS; k0 += 16) {
        float4 pv = *(const float4*)(P + (size_t)lr*SS + k0 + lc);
        float e0 = expf(pv.x - rm), e1 = expf(pv.y - rm);
        float e2 = expf(pv.z - rm), e3 = expf(pv.w - rm);
        psumv += e0 + e1 + e2 + e3;
        Ps[lc+0][lr] = e0; Ps[lc+1][lr] = e1; Ps[lc+2][lr] = e2; Ps[lc+3][lr] = e3;
        *(float4*)&Vs[vr][vc] = *(const float4*)(V + (size_t)(k0 + vr)*QKVLD + vc);
        __syncthreads();
        #pragma unroll
        for (int kk = 0; kk < 16; kk++) {
            float4 ra = *(const float4*)&Ps[kk][ty << 2], rb = *(const float4*)&Vs[kk][tx << 2];
            float ar[4] = {ra.x,ra.y,ra.z,ra.w}, br[4] = {rb.x,rb.y,rb.z,rb.w};
            #pragma unroll
            for (int i = 0; i < 4; i++)
                #pragma unroll
                for (int j = 0; j < 4; j++) acc[i][j] += ar[i]*br[j];
        }
        __syncthreads();
    }
    pm[lr][t & 3] = psumv;
    __syncthreads();
    if (t < 64)
        rowinv[t] = 1.0f/(pm[t][0] + pm[t][1] + pm[t][2] + pm[t][3]);
    __syncthreads();
    #pragma unroll
    for (int i = 0; i < 4; i++) {
        int qrow = (ty << 2) + i;
        float inv = rowinv[qrow];
        #pragma unroll
        for (int j = 0; j < 4; j++) {
            size_t idx = (size_t)(b*SS + q0 + qrow)*DD + h*DHH + (tx << 2) + j;
            __nv_bfloat16 hh, ll; split_hl(acc[i][j]*inv, hh, ll);
            oh[idx] = hh; ol[idx] = ll;
        }
    }
}

// ---------------- residual add + LayerNorm (+hi/lo) ----------------
__global__ void __launch_bounds__(256)
add_ln(const float* __restrict__ x1, const float* __restrict__ x2,
       const float* __restrict__ g, const float* __restrict__ bb,
       float* __restrict__ y, __nv_bfloat16* __restrict__ yh, __nv_bfloat16* __restrict__ yl)
{
    __shared__ float red[256];
    const int row = blockIdx.x, t = threadIdx.x;
    const size_t base = (size_t)row*DD;
    float a = x1[base+t] + x2[base+t];
    float c = x1[base+t+256] + x2[base+t+256];
    red[t] = a + c; __syncthreads();
    for (int o = 128; o > 0; o >>= 1) { if (t < o) red[t] += red[t+o]; __syncthreads(); }
    float mu = red[0]*(1.0f/DD); __syncthreads();
    float da = a - mu, dc = c - mu;
    red[t] = da*da + dc*dc; __syncthreads();
    for (int o = 128; o > 0; o >>= 1) { if (t < o) red[t] += red[t+o]; __syncthreads(); }
    float inv = rsqrtf(red[0]*(1.0f/DD) + 1e-6f);
    float v0 = da*inv*g[t] + bb[t], v1 = dc*inv*g[t+256] + bb[t+256];
    y[base+t] = v0; y[base+t+256] = v1;
    __nv_bfloat16 hh, ll;
    split_hl(v0, hh, ll); yh[base+t] = hh;     yl[base+t] = ll;
    split_hl(v1, hh, ll); yh[base+t+256] = hh; yl[base+t+256] = ll;
}

// ---------------- launch ----------------
extern "C" void kernel_launch(void* const* d_in, const int* in_sizes, int n_in,
                              void* d_out, int out_size)
{
    const int*   tokens = (const int*)d_in[0];
    const float* en_out = (const float*)d_in[1];
    const float* en_pad = (const float*)d_in[2];
    const float* emb    = (const float*)d_in[3];
    const float* sa_w = (const float*)d_in[4],  *sa_b = (const float*)d_in[5];
    const float* ca_w = (const float*)d_in[6],  *ca_b = (const float*)d_in[7];
    const float* ff_w1 = (const float*)d_in[8], *ff_b1 = (const float*)d_in[9];
    const float* ff_w2 = (const float*)d_in[10],*ff_b2 = (const float*)d_in[11];
    const float* ln_g = (const float*)d_in[12], *ln_b = (const float*)d_in[13];
    const float* out_w = (const float*)d_in[14],*out_b = (const float*)d_in[15];
    float* out = (float*)d_out;

    float *x,*h,*a,*qkv,*sc,*pr,*dp;
    cudaGetSymbolAddress((void**)&x,g_x); cudaGetSymbolAddress((void**)&h,g_h);
    cudaGetSymbolAddress((void**)&a,g_a); cudaGetSymbolAddress((void**)&qkv,g_qkv);
    cudaGetSymbolAddress((void**)&sc,g_sc); cudaGetSymbolAddress((void**)&pr,g_pr);
    cudaGetSymbolAddress((void**)&dp,g_dp);
    __nv_bfloat16 *wsah,*wsal,*wcah,*wcal,*wf1h,*wf1l,*wf2h,*wf2l,*woh,*wol,*enh,*enl;
    __nv_bfloat16 *xh,*xl,*hh,*hl,*ah,*al,*aoh,*aol,*ffh,*ffl;
    cudaGetSymbolAddress((void**)&wsah,g_wsa_h); cudaGetSymbolAddress((void**)&wsal,g_wsa_l);
    cudaGetSymbolAddress((void**)&wcah,g_wca_h); cudaGetSymbolAddress((void**)&wcal,g_wca_l);
    cudaGetSymbolAddress((void**)&wf1h,g_wf1_h); cudaGetSymbolAddress((void**)&wf1l,g_wf1_l);
    cudaGetSymbolAddress((void**)&wf2h,g_wf2_h); cudaGetSymbolAddress((void**)&wf2l,g_wf2_l);
    cudaGetSymbolAddress((void**)&woh,g_wo_h);   cudaGetSymbolAddress((void**)&wol,g_wo_l);
    cudaGetSymbolAddress((void**)&enh,g_en_h);   cudaGetSymbolAddress((void**)&enl,g_en_l);
    cudaGetSymbolAddress((void**)&xh,g_xh);   cudaGetSymbolAddress((void**)&xl,g_xl);
    cudaGetSymbolAddress((void**)&hh,g_hh);   cudaGetSymbolAddress((void**)&hl,g_hl2);
    cudaGetSymbolAddress((void**)&ah,g_ah);   cudaGetSymbolAddress((void**)&al,g_al);
    cudaGetSymbolAddress((void**)&aoh,g_aoh); cudaGetSymbolAddress((void**)&aol,g_aol);
    cudaGetSymbolAddress((void**)&ffh,g_ffh); cudaGetSymbolAddress((void**)&ffl,g_ffl);

    cudaFuncSetAttribute(tgemm<0,0,128>, cudaFuncAttributeMaxDynamicSharedMemorySize, DSM(128));
    cudaFuncSetAttribute(tgemm<0,0,64>,  cudaFuncAttributeMaxDynamicSharedMemorySize, DSM(64));
    cudaFuncSetAttribute(tgemm<1,1,128>, cudaFuncAttributeMaxDynamicSharedMemorySize, DSM(128));
    cudaFuncSetAttribute(attn_scores_mma<0>, cudaFuncAttributeMaxDynamicSharedMemorySize, SC_DSMEM);
    cudaFuncSetAttribute(attn_scores_mma<1>, cudaFuncAttributeMaxDynamicSharedMemorySize, SC_DSMEM);

    cvt_hl<<<NW_SA/4/256, 256>>>(sa_w, wsah, wsal, NW_SA/4);
    cvt_hl<<<NW_SA/4/256, 256>>>(ca_w, wcah, wcal, NW_SA/4);
    cvt_hl<<<NW_F1/4/256, 256>>>(ff_w1, wf1h, wf1l, NW_F1/4);
    cvt_hl<<<NW_F1/4/256, 256>>>(ff_w2, wf2h, wf2l, NW_F1/4);
    cvt_hl<<<NW_OUT/4/256, 256>>>(out_w, woh, wol, NW_OUT/4);
    cvt_hl<<<MM*DD/4/256, 256>>>(en_out, enh, enl, MM*DD/4);

    embed_kernel<<<MM, 256>>>(tokens, emb, x, xh, xl, dp);

    const dim3 gS(SS/128, SS/128, BB*HH), gV(1, SS/64, BB*HH);
    for (int i = 0; i < LL; i++) {
        const size_t w4 = (size_t)i*4*DD*DD, b4 = (size_t)i*4*DD;
        // self attention
        tgemm<0,0,128><<<dim3(QKVLD/128, MM/128), 256, DSM(128)>>>(
            xh, xl, wsah+w4, wsal+w4, sa_b+b4, qkv, 0, 0, DD, QKVLD);
        attn_scores_mma<1><<<gS, 256, SC_DSMEM>>>(qkv, dp, sc);
        attn_av_sm<<<gV, 256>>>(sc, qkv, aoh, aol);
        tgemm<0,0,64><<<dim3(DD/128, MM/64), 256, DSM(64)>>>(
            aoh, aol, wsah+w4+3*DD*DD, wsal+w4+3*DD*DD, sa_b+b4+3*DD, pr, 0, 0, DD, DD);
        add_ln<<<MM, 256>>>(x, pr, ln_g+(size_t)(i*3+0)*DD, ln_b+(size_t)(i*3+0)*DD, h, hh, hl);
        // cross attention
        tgemm<0,0,64><<<dim3(DD/128, MM/64), 256, DSM(64)>>>(
            hh, hl, wcah+w4, wcal+w4, ca_b+b4, qkv, 0, 0, DD, QKVLD);
        tgemm<0,0,128><<<dim3(2*DD/128, MM/128), 256, DSM(128)>>>(
            enh, enl, wcah+w4+DD*DD, wcal+w4+DD*DD, ca_b+b4+DD, qkv+DD, 0, 0, DD, QKVLD);
        attn_scores_mma<0><<<gS, 256, SC_DSMEM>>>(qkv, en_pad, sc);
        attn_av_sm<<<gV, 256>>>(sc, qkv, aoh, aol);
        tgemm<0,0,64><<<dim3(DD/128, MM/64), 256, DSM(64)>>>(
            aoh, aol, wcah+w4+3*DD*DD, wcal+w4+3*DD*DD, ca_b+b4+3*DD, pr, 0, 0, DD, DD);
        add_ln<<<MM, 256>>>(h, pr, ln_g+(size_t)(i*3+1)*DD, ln_b+(size_t)(i*3+1)*DD, a, ah, al);
        // feed forward
        tgemm<1,1,128><<<dim3(FFD/128, MM/128), 256, DSM(128)>>>(
            ah, al, wf1h+(size_t)i*FFD*DD, wf1l+(size_t)i*FFD*DD, ff_b1+(size_t)i*FFD,
            0, ffh, ffl, DD, FFD);
        tgemm<0,0,64><<<dim3(DD/128, MM/64), 256, DSM(64)>>>(
            ffh, ffl, wf2h+(size_t)i*FFD*DD, wf2l+(size_t)i*FFD*DD, ff_b2+(size_t)i*DD,
            pr, 0, 0, FFD, DD);
        add_ln<<<MM, 256>>>(a, pr, ln_g+(size_t)(i*3+2)*DD, ln_b+(size_t)(i*3+2)*DD, x, xh, xl);
    }
    tgemm<0,0,128><<<dim3(VV/128, MM/128), 256, DSM(128)>>>(
        xh, xl, woh, wol, out_b, out, 0, 0, DD, VV);
}

// round 9
// speedup vs baseline: 2.0539x; 1.0426x over previous
#include <cuda_runtime.h>
#include <cuda_bf16.h>
#include <math.h>
#include <stdint.h>

typedef unsigned int u32; typedef unsigned long long u64;
#define BB 4
#define SS 512
#define DD 512
#define HH 8
#define DHH 64
#define FFD 2048
#define LL 6
#define VV 32000
#define MM (BB*SS)
#define QKVLD (3*DD)

__device__ float g_x[MM*DD], g_h[MM*DD], g_a[MM*DD], g_qkv[MM*3*DD];
__device__ float g_sc[BB*HH*SS*SS], g_pr[MM*DD], g_dp[MM];
__device__ float g_pm[BB*HH*SS*4];
#define NW_SA (LL*4*DD*DD)
#define NW_F1 (LL*FFD*DD)
#define NW_OUT (VV*DD)
__device__ __nv_bfloat16 g_wsa_h[NW_SA], g_wsa_l[NW_SA], g_wca_h[NW_SA], g_wca_l[NW_SA];
__device__ __nv_bfloat16 g_wf1_h[NW_F1], g_wf1_l[NW_F1], g_wf2_h[NW_F1], g_wf2_l[NW_F1];
__device__ __nv_bfloat16 g_wo_h[NW_OUT], g_wo_l[NW_OUT], g_en_h[MM*DD], g_en_l[MM*DD];
__device__ __nv_bfloat16 g_xh[MM*DD], g_xl[MM*DD], g_hh[MM*DD], g_hl2[MM*DD];
__device__ __nv_bfloat16 g_ah[MM*DD], g_al[MM*DD], g_aoh[MM*DD], g_aol[MM*DD];
__device__ __nv_bfloat16 g_ffh[MM*FFD], g_ffl[MM*FFD];

__device__ __forceinline__ u32 smem_u32(const void* p) {
    u32 a; asm("{ .reg .u64 t; cvta.to.shared.u64 t, %1; cvt.u32.u64 %0, t; }" : "=r"(a) : "l"(p)); return a;
}
__device__ __forceinline__ void ldsm4(u32& r0, u32& r1, u32& r2, u32& r3, u32 addr) {
    asm volatile("ldmatrix.sync.aligned.m8n8.x4.shared.b16 {%0,%1,%2,%3}, [%4];"
                 : "=r"(r0), "=r"(r1), "=r"(r2), "=r"(r3) : "r"(addr));
}
__device__ __forceinline__ void mma16816(float* d, const u32* a, const u32* b) {
    asm volatile("mma.sync.aligned.m16n8k16.row.col.f32.bf16.bf16.f32 "
                 "{%0,%1,%2,%3}, {%4,%5,%6,%7}, {%8,%9}, {%0,%1,%2,%3};"
                 : "+f"(d[0]), "+f"(d[1]), "+f"(d[2]), "+f"(d[3])
                 : "r"(a[0]), "r"(a[1]), "r"(a[2]), "r"(a[3]), "r"(b[0]), "r"(b[1]));
}
__device__ __forceinline__ void cpa16(u32 saddr, const void* gaddr) {
    asm volatile("cp.async.cg.shared.global [%0], [%1], 16;" :: "r"(saddr), "l"(gaddr));
}
__device__ __forceinline__ void cpa_commit() { asm volatile("cp.async.commit_group;"); }
__device__ __forceinline__ void cpa_wait1()  { asm volatile("cp.async.wait_group 1;"); }
__device__ __forceinline__ void split_hl(float v, __nv_bfloat16& h, __nv_bfloat16& l) {
    h = __float2bfloat16(v); l = __float2bfloat16(v - __bfloat162float(h));
}

__global__ void cvt_hl(const float* __restrict__ s, __nv_bfloat16* __restrict__ hi,
                       __nv_bfloat16* __restrict__ lo, int n4) {
    int i = blockIdx.x*blockDim.x + threadIdx.x;
    if (i >= n4) return;
    float4 v = ((const float4*)s)[i];
    __nv_bfloat16 h, l;
    split_hl(v.x,h,l); hi[i*4+0]=h; lo[i*4+0]=l;
    split_hl(v.y,h,l); hi[i*4+1]=h; lo[i*4+1]=l;
    split_hl(v.z,h,l); hi[i*4+2]=h; lo[i*4+2]=l;
    split_hl(v.w,h,l); hi[i*4+3]=h; lo[i*4+3]=l;
}

// ======== HMMA split-3 GEMM, cp.async 3-stage, BK=64, M-tile templated =======
#define BK 64
#define SPITCH 72
#define TG_STAGES 3
#define WTILEE (128*SPITCH)
template<int RELU, int OUTHL, int MT>
__global__ void __launch_bounds__(256)
tgemm(const __nv_bfloat16* __restrict__ Ah, const __nv_bfloat16* __restrict__ Al,
      const __nv_bfloat16* __restrict__ Wh, const __nv_bfloat16* __restrict__ Wl,
      const float* __restrict__ bias, float* __restrict__ C,
      __nv_bfloat16* __restrict__ Ch, __nv_bfloat16* __restrict__ Cl, int K, int ldc)
{
    constexpr int ATILEE = MT*SPITCH;
    constexpr int STAGEE = ATILEE + WTILEE;
    constexpr int WM = MT/32;
    extern __shared__ __align__(16) __nv_bfloat16 sm[];
    const int t = threadIdx.x, lane = t & 31, wid = t >> 5;
    const int m0 = blockIdx.y*MT, n0 = blockIdx.x*128;
    const int wm = wid >> 2, wn = wid & 3;
    const int mbase = wm*(MT/2), nbase = wn*32;
    const int mat = lane >> 3, rowin = lane & 7;
    const int a_row = (mat & 1)*8 + rowin, a_col = (mat >> 1)*8;
    const int b_row = (mat >> 1)*8 + rowin, b_col = (mat & 1)*8;
    const int wlrow = t >> 1, wlcol = (t & 1)*32;
    const int alrow = (MT == 128) ? (t >> 1) : (t >> 2);
    const int alcol = (MT == 128) ? ((t & 1)*32) : ((t & 3)*16);
    const int kc = K/BK, nch = 3*kc;
    const u32 sbase = smem_u32(&sm[0]);

    float acc[WM][4][4];
    #pragma unroll
    for (int i = 0; i < WM; i++)
        #pragma unroll
        for (int j = 0; j < 4; j++)
            #pragma unroll
            for (int q = 0; q < 4; q++) acc[i][j][q] = 0.f;

    auto issue = [&](int c) {
        const int s = c % TG_STAGES;
        const int seg = c / kc, kq = (c - seg*kc)*BK;
        const __nv_bfloat16* as = ((seg == 2) ? Al : Ah) + (size_t)(m0+alrow)*K + kq + alcol;
        const __nv_bfloat16* ws = ((seg == 1) ? Wl : Wh) + (size_t)(n0+wlrow)*K + kq + wlcol;
        const u32 da = sbase + (u32)((s*STAGEE + alrow*SPITCH + alcol)*2);
        const u32 dw = sbase + (u32)((s*STAGEE + ATILEE + wlrow*SPITCH + wlcol)*2);
        if (MT == 128) {
            cpa16(da, as); cpa16(da+16, as+8); cpa16(da+32, as+16); cpa16(da+48, as+24);
        } else {
            cpa16(da, as); cpa16(da+16, as+8);
        }
        cpa16(dw, ws); cpa16(dw+16, ws+8); cpa16(dw+32, ws+16); cpa16(dw+48, ws+24);
    };

    #pragma unroll
    for (int c = 0; c < TG_STAGES-1; c++) { issue(c); cpa_commit(); }

    for (int c = 0; c < nch; ++c) {
        cpa_wait1();
        __syncthreads();
        const int s = c % TG_STAGES;
        const u32 abase = sbase + (u32)(s*STAGEE*2);
        const u32 wbase = abase + (u32)(ATILEE*2);
        #pragma unroll
        for (int ks = 0; ks < BK/16; ks++) {
            u32 af[WM][4], bfr[2][4];
            #pragma unroll
            for (int mi = 0; mi < WM; mi++) {
                u32 ad = abase + (u32)(((mbase + mi*16 + a_row)*SPITCH + ks*16 + a_col)*2);
                ldsm4(af[mi][0], af[mi][1], af[mi][2], af[mi][3], ad);
            }
            #pragma unroll
            for (int g = 0; g < 2; g++) {
                u32 bd = wbase + (u32)(((nbase + g*16 + b_row)*SPITCH + ks*16 + b_col)*2);
                ldsm4(bfr[g][0], bfr[g][1], bfr[g][2], bfr[g][3], bd);
            }
            #pragma unroll
            for (int mi = 0; mi < WM; mi++)
                #pragma unroll
                for (int ni = 0; ni < 4; ni++)
                    mma16816(acc[mi][ni], af[mi], &bfr[ni >> 1][(ni & 1)*2]);
        }
        const int cn = c + TG_STAGES - 1;
        if (cn < nch) issue(cn);
        cpa_commit();
    }

    const int r = lane >> 2, c2 = (lane & 3) << 1;
    #pragma unroll
    for (int mi = 0; mi < WM; mi++) {
        #pragma unroll
        for (int ni = 0; ni < 4; ni++) {
            const int m = m0 + mbase + mi*16 + r;
            const int n = n0 + nbase + ni*8 + c2;
            float b0 = bias[n], b1 = bias[n+1];
            float v0 = acc[mi][ni][0] + b0, v1 = acc[mi][ni][1] + b1;
            float v2 = acc[mi][ni][2] + b0, v3 = acc[mi][ni][3] + b1;
            if (RELU) { v0=fmaxf(v0,0.f); v1=fmaxf(v1,0.f); v2=fmaxf(v2,0.f); v3=fmaxf(v3,0.f); }
            if (OUTHL) {
                __nv_bfloat16 h, l;
                size_t i0 = (size_t)m*ldc + n, i1 = (size_t)(m+8)*ldc + n;
                split_hl(v0,h,l); Ch[i0]=h;   Cl[i0]=l;
                split_hl(v1,h,l); Ch[i0+1]=h; Cl[i0+1]=l;
                split_hl(v2,h,l); Ch[i1]=h;   Cl[i1]=l;
                split_hl(v3,h,l); Ch[i1+1]=h; Cl[i1+1]=l;
            } else {
                *(float2*)(C + (size_t)m*ldc + n)     = make_float2(v0, v1);
                *(float2*)(C + (size_t)(m+8)*ldc + n) = make_float2(v2, v3);
            }
        }
    }
}
#define DSM(MT) (TG_STAGES*((MT)+128)*SPITCH*2)

// ======== attention scores via HMMA split-3, + fused per-tile row max =======
#define SC_TILE (128*SPITCH)
#define SC_DSMEM (4*SC_TILE*2)
template<int CAUSAL>
__global__ void __launch_bounds__(256)
attn_scores_mma(const float* __restrict__ qkv, const float* __restrict__ mask,
                float* __restrict__ scores, float* __restrict__ pmax)
{
    extern __shared__ __align__(16) __nv_bfloat16 sm[];
    __shared__ float spm[128][4];
    __nv_bfloat16 *Qh = sm, *Ql = sm + SC_TILE, *Kh = sm + 2*SC_TILE, *Kl = sm + 3*SC_TILE;
    const int z = blockIdx.z, b = z >> 3, h = z & 7;
    const int q0 = blockIdx.y*128, k0v = blockIdx.x*128;
    const int t = threadIdx.x, lane = t & 31, wid = t >> 5;

    #pragma unroll
    for (int i = 0; i < 8; i++) {
        int fi = t + i*256;
        int row = fi >> 4, col = (fi & 15)*4;
        float4 qv = *(const float4*)(qkv + (size_t)(b*SS + q0 + row)*QKVLD + h*DHH + col);
        float4 kv = *(const float4*)(qkv + (size_t)(b*SS + k0v + row)*QKVLD + DD + h*DHH + col);
        __nv_bfloat16 hh, ll;
        int o = row*SPITCH + col;
        split_hl(qv.x,hh,ll); Qh[o+0]=hh; Ql[o+0]=ll;
        split_hl(qv.y,hh,ll); Qh[o+1]=hh; Ql[o+1]=ll;
        split_hl(qv.z,hh,ll); Qh[o+2]=hh; Ql[o+2]=ll;
        split_hl(qv.w,hh,ll); Qh[o+3]=hh; Ql[o+3]=ll;
        split_hl(kv.x,hh,ll); Kh[o+0]=hh; Kl[o+0]=ll;
        split_hl(kv.y,hh,ll); Kh[o+1]=hh; Kl[o+1]=ll;
        split_hl(kv.z,hh,ll); Kh[o+2]=hh; Kl[o+2]=ll;
        split_hl(kv.w,hh,ll); Kh[o+3]=hh; Kl[o+3]=ll;
    }
    __syncthreads();

    const int wm = wid >> 2, wn = wid & 3;
    const int mbase = wm*64, nbase = wn*32;
    const int mat = lane >> 3, rowin = lane & 7;
    const int a_row = (mat & 1)*8 + rowin, a_col = (mat >> 1)*8;
    const int b_row = (mat >> 1)*8 + rowin, b_col = (mat & 1)*8;
    float acc[4][4][4];
    #pragma unroll
    for (int i = 0; i < 4; i++)
        #pragma unroll
        for (int j = 0; j < 4; j++)
            #pragma unroll
            for (int q = 0; q < 4; q++) acc[i][j][q] = 0.f;

    #pragma unroll
    for (int seg = 0; seg < 3; seg++) {
        const u32 abase = smem_u32((seg == 2) ? Ql : Qh);
        const u32 wbase = smem_u32((seg == 1) ? Kl : Kh);
        #pragma unroll
        for (int ks = 0; ks < 4; ks++) {
            u32 af[4][4], bfr[2][4];
            #pragma unroll
            for (int mi = 0; mi < 4; mi++) {
                u32 ad = abase + (u32)(((mbase + mi*16 + a_row)*SPITCH + ks*16 + a_col)*2);
                ldsm4(af[mi][0], af[mi][1], af[mi][2], af[mi][3], ad);
            }
            #pragma unroll
            for (int g = 0; g < 2; g++) {
                u32 bd = wbase + (u32)(((nbase + g*16 + b_row)*SPITCH + ks*16 + b_col)*2);
                ldsm4(bfr[g][0], bfr[g][1], bfr[g][2], bfr[g][3], bd);
            }
            #pragma unroll
            for (int mi = 0; mi < 4; mi++)
                #pragma unroll
                for (int ni = 0; ni < 4; ni++)
                    mma16816(acc[mi][ni], af[mi], &bfr[ni >> 1][(ni & 1)*2]);
        }
    }

    const int r = lane >> 2, c2 = (lane & 3) << 1;
    float rmax[4][2];
    #pragma unroll
    for (int mi = 0; mi < 4; mi++) { rmax[mi][0] = -1e30f; rmax[mi][1] = -1e30f; }
    #pragma unroll
    for (int mi = 0; mi < 4; mi++) {
        #pragma unroll
        for (int ni = 0; ni < 4; ni++) {
            #pragma unroll
            for (int half = 0; half < 2; half++) {
                const int m = q0 + mbase + mi*16 + r + half*8;
                const int n = k0v + nbase + ni*8 + c2;
                float mv0 = mask[b*SS + n], mv1 = mask[b*SS + n + 1];
                if (CAUSAL && n   > m) mv0 = 1.0f;
                if (CAUSAL && n+1 > m) mv1 = 1.0f;
                float v0 = acc[mi][ni][half*2+0]*0.125f - mv0*1e6f;
                float v1 = acc[mi][ni][half*2+1]*0.125f - mv1*1e6f;
                rmax[mi][half] = fmaxf(rmax[mi][half], fmaxf(v0, v1));
                *(float2*)(scores + ((size_t)z*SS + m)*SS + n) = make_float2(v0, v1);
            }
        }
    }
    #pragma unroll
    for (int mi = 0; mi < 4; mi++)
        #pragma unroll
        for (int half = 0; half < 2; half++) {
            float mv = rmax[mi][half];
            mv = fmaxf(mv, __shfl_xor_sync(0xFFFFFFFFu, mv, 1));
            mv = fmaxf(mv, __shfl_xor_sync(0xFFFFFFFFu, mv, 2));
            if ((lane & 3) == 0)
                spm[mbase + mi*16 + r + half*8][wn] = mv;
        }
    __syncthreads();
    if (t < 128) {
        float mv = fmaxf(fmaxf(spm[t][0], spm[t][1]), fmaxf(spm[t][2], spm[t][3]));
        pmax[((size_t)z*SS + q0 + t)*4 + blockIdx.x] = mv;
    }
}

// ---------------- embedding ----------------
__global__ void embed_kernel(const int* __restrict__ tokens, const float* __restrict__ emb,
                             float* __restrict__ x, __nv_bfloat16* __restrict__ xh,
                             __nv_bfloat16* __restrict__ xl, float* __restrict__ depad)
{
    int row = blockIdx.x, s = row & (SS-1), tok = tokens[row];
    if (threadIdx.x == 0) depad[row] = (tok == 0) ? 1.0f : 0.0f;
    const float sq = sqrtf((float)DD);
    for (int d = threadIdx.x; d < DD; d += blockDim.x) {
        float i = (float)((d >> 1) << 1)/(float)DD;
        float em = (float)s*powf(10000.0f, -i);
        float pe = ((d & 1) == 0) ? sinf(em) : cosf(em);
        float v = emb[(size_t)tok*DD + d]*sq + pe;
        x[(size_t)row*DD + d] = v;
        __nv_bfloat16 h, l; split_hl(v, h, l);
        xh[(size_t)row*DD + d] = h; xl[(size_t)row*DD + d] = l;
    }
}

// ======== attention AV via HMMA split-3, fused softmax, single pass =========
// Tile 128 q x 64 dh per block; K-loop chunks of 64; P exp'd+split in smem,
// V transposed to [d][k] hi/lo smem so B operand uses the standard ldsm path.
#define AV_SP 72
#define AV_DSMEM ((2*128 + 2*64)*AV_SP*2)
__global__ void __launch_bounds__(256)
attn_av_mma(const float* __restrict__ S, const float* __restrict__ pmax,
            const float* __restrict__ qkv,
            __nv_bfloat16* __restrict__ oh, __nv_bfloat16* __restrict__ ol)
{
    extern __shared__ __align__(16) __nv_bfloat16 sm[];
    __nv_bfloat16 *Ph = sm, *Pl = sm + 128*AV_SP;
    __nv_bfloat16 *Vh = sm + 2*128*AV_SP, *Vl = Vh + 64*AV_SP;
    __shared__ float rowm[128], rowinv[128];
    __shared__ float psum2[128][2];
    const int z = blockIdx.z, b = z >> 3, h = z & 7;
    const int q0 = blockIdx.y*128;
    const int t = threadIdx.x, lane = t & 31, wid = t >> 5;

    if (t < 128) {
        const float* pp = pmax + ((size_t)z*SS + q0 + t)*4;
        rowm[t] = fmaxf(fmaxf(pp[0], pp[1]), fmaxf(pp[2], pp[3]));
    }
    __syncthreads();

    const int prow = t >> 1, pc0 = (t & 1)*32;
    const int vrow = t >> 2, vc0 = (t & 3)*16;
    const int wm = wid >> 2, wn = wid & 3;
    const int mbase = wm*64, nbase = wn*16;
    const int mat = lane >> 3, rowin = lane & 7;
    const int a_row = (mat & 1)*8 + rowin, a_col = (mat >> 1)*8;
    const int b_row = (mat >> 1)*8 + rowin, b_col = (mat & 1)*8;

    float acc[4][2][4];
    #pragma unroll
    for (int i = 0; i < 4; i++)
        #pragma unroll
        for (int j = 0; j < 2; j++)
            #pragma unroll
            for (int q = 0; q < 4; q++) acc[i][j][q] = 0.f;
    float psum = 0.f;
    const float rm = rowm[prow];
    const float* Srow = S + ((size_t)z*SS + q0 + prow)*SS + pc0;
    const float* Vbase = qkv + (size_t)(b*SS)*QKVLD + 2*DD + h*DHH + vc0;

    for (int k0 = 0; k0 < SS; k0 += 64) {
        // P chunk: exp + split, rows fixed per thread
        #pragma unroll
        for (int i = 0; i < 8; i++) {
            float4 v = *(const float4*)(Srow + k0 + i*4);
            float e0 = expf(v.x - rm), e1 = expf(v.y - rm);
            float e2 = expf(v.z - rm), e3 = expf(v.w - rm);
            psum += e0 + e1 + e2 + e3;
            int o = prow*AV_SP + pc0 + i*4;
            __nv_bfloat16 hh, ll;
            split_hl(e0,hh,ll); Ph[o+0]=hh; Pl[o+0]=ll;
            split_hl(e1,hh,ll); Ph[o+1]=hh; Pl[o+1]=ll;
            split_hl(e2,hh,ll); Ph[o+2]=hh; Pl[o+2]=ll;
            split_hl(e3,hh,ll); Ph[o+3]=hh; Pl[o+3]=ll;
        }
        // V chunk 64x64 fp32 -> transposed [d][k] bf16 hi/lo
        #pragma unroll
        for (int i = 0; i < 4; i++) {
            float4 v = *(const float4*)(Vbase + (size_t)(k0 + vrow)*QKVLD + i*4);
            __nv_bfloat16 hh, ll;
            int dbase = vc0 + i*4;
            split_hl(v.x,hh,ll); Vh[(dbase+0)*AV_SP + vrow]=hh; Vl[(dbase+0)*AV_SP + vrow]=ll;
            split_hl(v.y,hh,ll); Vh[(dbase+1)*AV_SP + vrow]=hh; Vl[(dbase+1)*AV_SP + vrow]=ll;
            split_hl(v.z,hh,ll); Vh[(dbase+2)*AV_SP + vrow]=hh; Vl[(dbase+2)*AV_SP + vrow]=ll;
            split_hl(v.w,hh,ll); Vh[(dbase+3)*AV_SP + vrow]=hh; Vl[(dbase+3)*AV_SP + vrow]=ll;
        }
        __syncthreads();
        #pragma unroll
        for (int seg = 0; seg < 3; seg++) {
            const u32 abase = smem_u32((seg == 2) ? Pl : Ph);
            const u32 wbase = smem_u32((seg == 1) ? Vl : Vh);
            #pragma unroll
            for (int ks = 0; ks < 4; ks++) {
                u32 af[4][4], bfr[4];
                #pragma unroll
                for (int mi = 0; mi < 4; mi++) {
                    u32 ad = abase + (u32)(((mbase + mi*16 + a_row)*AV_SP + ks*16 + a_col)*2);
                    ldsm4(af[mi][0], af[mi][1], af[mi][2], af[mi][3], ad);
                }
                u32 bd = wbase + (u32)(((nbase + b_row)*AV_SP + ks*16 + b_col)*2);
                ldsm4(bfr[0], bfr[1], bfr[2], bfr[3], bd);
                #pragma unroll
                for (int mi = 0; mi < 4; mi++)
                    #pragma unroll
                    for (int ni = 0; ni < 2; ni++)
                        mma16816(acc[mi][ni], af[mi], &bfr[ni*2]);
            }
        }
        __syncthreads();
    }
    psum2[prow][t & 1] = psum;
    __syncthreads();
    if (t < 128) rowinv[t] = 1.0f/(psum2[t][0] + psum2[t][1]);
    __syncthreads();

    const int r = lane >> 2, c2 = (lane & 3) << 1;
    #pragma unroll
    for (int mi = 0; mi < 4; mi++) {
        #pragma unroll
        for (int ni = 0; ni < 2; ni++) {
            #pragma unroll
            for (int half = 0; half < 2; half++) {
                const int ml = mbase + mi*16 + r + half*8;
                const int n = nbase + ni*8 + c2;
                float inv = rowinv[ml];
                float v0 = acc[mi][ni][half*2+0]*inv;
                float v1 = acc[mi][ni][half*2+1]*inv;
                size_t idx = (size_t)(b*SS + q0 + ml)*DD + h*DHH + n;
                __nv_bfloat16 hh, ll;
                split_hl(v0,hh,ll); oh[idx]=hh;   ol[idx]=ll;
                split_hl(v1,hh,ll); oh[idx+1]=hh; ol[idx+1]=ll;
            }
        }
    }
}

// ---------------- residual add + LayerNorm (+hi/lo) ----------------
__global__ void __launch_bounds__(256)
add_ln(const float* __restrict__ x1, const float* __restrict__ x2,
       const float* __restrict__ g, const float* __restrict__ bb,
       float* __restrict__ y, __nv_bfloat16* __restrict__ yh, __nv_bfloat16* __restrict__ yl)
{
    __shared__ float red[256];
    const int row = blockIdx.x, t = threadIdx.x;
    const size_t base = (size_t)row*DD;
    float a = x1[base+t] + x2[base+t];
    float c = x1[base+t+256] + x2[base+t+256];
    red[t] = a + c; __syncthreads();
    for (int o = 128; o > 0; o >>= 1) { if (t < o) red[t] += red[t+o]; __syncthreads(); }
    float mu = red[0]*(1.0f/DD); __syncthreads();
    float da = a - mu, dc = c - mu;
    red[t] = da*da + dc*dc; __syncthreads();
    for (int o = 128; o > 0; o >>= 1) { if (t < o) red[t] += red[t+o]; __syncthreads(); }
    float inv = rsqrtf(red[0]*(1.0f/DD) + 1e-6f);
    float v0 = da*inv*g[t] + bb[t], v1 = dc*inv*g[t+256] + bb[t+256];
    y[base+t] = v0; y[base+t+256] = v1;
    __nv_bfloat16 hh, ll;
    split_hl(v0, hh, ll); yh[base+t] = hh;     yl[base+t] = ll;
    split_hl(v1, hh, ll); yh[base+t+256] = hh; yl[base+t+256] = ll;
}

// ---------------- launch ----------------
extern "C" void kernel_launch(void* const* d_in, const int* in_sizes, int n_in,
                              void* d_out, int out_size)
{
    const int*   tokens = (const int*)d_in[0];
    const float* en_out = (const float*)d_in[1];
    const float* en_pad = (const float*)d_in[2];
    const float* emb    = (const float*)d_in[3];
    const float* sa_w = (const float*)d_in[4],  *sa_b = (const float*)d_in[5];
    const float* ca_w = (const float*)d_in[6],  *ca_b = (const float*)d_in[7];
    const float* ff_w1 = (const float*)d_in[8], *ff_b1 = (const float*)d_in[9];
    const float* ff_w2 = (const float*)d_in[10],*ff_b2 = (const float*)d_in[11];
    const float* ln_g = (const float*)d_in[12], *ln_b = (const float*)d_in[13];
    const float* out_w = (const float*)d_in[14],*out_b = (const float*)d_in[15];
    float* out = (float*)d_out;

    float *x,*h,*a,*qkv,*sc,*pr,*dp,*pm;
    cudaGetSymbolAddress((void**)&x,g_x); cudaGetSymbolAddress((void**)&h,g_h);
    cudaGetSymbolAddress((void**)&a,g_a); cudaGetSymbolAddress((void**)&qkv,g_qkv);
    cudaGetSymbolAddress((void**)&sc,g_sc); cudaGetSymbolAddress((void**)&pr,g_pr);
    cudaGetSymbolAddress((void**)&dp,g_dp); cudaGetSymbolAddress((void**)&pm,g_pm);
    __nv_bfloat16 *wsah,*wsal,*wcah,*wcal,*wf1h,*wf1l,*wf2h,*wf2l,*woh,*wol,*enh,*enl;
    __nv_bfloat16 *xh,*xl,*hh,*hl,*ah,*al,*aoh,*aol,*ffh,*ffl;
    cudaGetSymbolAddress((void**)&wsah,g_wsa_h); cudaGetSymbolAddress((void**)&wsal,g_wsa_l);
    cudaGetSymbolAddress((void**)&wcah,g_wca_h); cudaGetSymbolAddress((void**)&wcal,g_wca_l);
    cudaGetSymbolAddress((void**)&wf1h,g_wf1_h); cudaGetSymbolAddress((void**)&wf1l,g_wf1_l);
    cudaGetSymbolAddress((void**)&wf2h,g_wf2_h); cudaGetSymbolAddress((void**)&wf2l,g_wf2_l);
    cudaGetSymbolAddress((void**)&woh,g_wo_h);   cudaGetSymbolAddress((void**)&wol,g_wo_l);
    cudaGetSymbolAddress((void**)&enh,g_en_h);   cudaGetSymbolAddress((void**)&enl,g_en_l);
    cudaGetSymbolAddress((void**)&xh,g_xh);   cudaGetSymbolAddress((void**)&xl,g_xl);
    cudaGetSymbolAddress((void**)&hh,g_hh);   cudaGetSymbolAddress((void**)&hl,g_hl2);
    cudaGetSymbolAddress((void**)&ah,g_ah);   cudaGetSymbolAddress((void**)&al,g_al);
    cudaGetSymbolAddress((void**)&aoh,g_aoh); cudaGetSymbolAddress((void**)&aol,g_aol);
    cudaGetSymbolAddress((void**)&ffh,g_ffh); cudaGetSymbolAddress((void**)&ffl,g_ffl);

    cudaFuncSetAttribute(tgemm<0,0,128>, cudaFuncAttributeMaxDynamicSharedMemorySize, DSM(128));
    cudaFuncSetAttribute(tgemm<0,0,64>,  cudaFuncAttributeMaxDynamicSharedMemorySize, DSM(64));
    cudaFuncSetAttribute(tgemm<1,1,128>, cudaFuncAttributeMaxDynamicSharedMemorySize, DSM(128));
    cudaFuncSetAttribute(attn_scores_mma<0>, cudaFuncAttributeMaxDynamicSharedMemorySize, SC_DSMEM);
    cudaFuncSetAttribute(attn_scores_mma<1>, cudaFuncAttributeMaxDynamicSharedMemorySize, SC_DSMEM);
    cudaFuncSetAttribute(attn_av_mma, cudaFuncAttributeMaxDynamicSharedMemorySize, AV_DSMEM);

    cvt_hl<<<NW_SA/4/256, 256>>>(sa_w, wsah, wsal, NW_SA/4);
    cvt_hl<<<NW_SA/4/256, 256>>>(ca_w, wcah, wcal, NW_SA/4);
    cvt_hl<<<NW_F1/4/256, 256>>>(ff_w1, wf1h, wf1l, NW_F1/4);
    cvt_hl<<<NW_F1/4/256, 256>>>(ff_w2, wf2h, wf2l, NW_F1/4);
    cvt_hl<<<NW_OUT/4/256, 256>>>(out_w, woh, wol, NW_OUT/4);
    cvt_hl<<<MM*DD/4/256, 256>>>(en_out, enh, enl, MM*DD/4);

    embed_kernel<<<MM, 256>>>(tokens, emb, x, xh, xl, dp);

    const dim3 gS(SS/128, SS/128, BB*HH), gV(1, SS/128, BB*HH);
    for (int i = 0; i < LL; i++) {
        const size_t w4 = (size_t)i*4*DD*DD, b4 = (size_t)i*4*DD;
        // self attention
        tgemm<0,0,128><<<dim3(QKVLD/128, MM/128), 256, DSM(128)>>>(
            xh, xl, wsah+w4, wsal+w4, sa_b+b4, qkv, 0, 0, DD, QKVLD);
        attn_scores_mma<1><<<gS, 256, SC_DSMEM>>>(qkv, dp, sc, pm);
        attn_av_mma<<<gV, 256, AV_DSMEM>>>(sc, pm, qkv, aoh, aol);
        tgemm<0,0,64><<<dim3(DD/128, MM/64), 256, DSM(64)>>>(
            aoh, aol, wsah+w4+3*DD*DD, wsal+w4+3*DD*DD, sa_b+b4+3*DD, pr, 0, 0, DD, DD);
        add_ln<<<MM, 256>>>(x, pr, ln_g+(size_t)(i*3+0)*DD, ln_b+(size_t)(i*3+0)*DD, h, hh, hl);
        // cross attention
        tgemm<0,0,64><<<dim3(DD/128, MM/64), 256, DSM(64)>>>(
            hh, hl, wcah+w4, wcal+w4, ca_b+b4, qkv, 0, 0, DD, QKVLD);
        tgemm<0,0,128><<<dim3(2*DD/128, MM/128), 256, DSM(128)>>>(
            enh, enl, wcah+w4+DD*DD, wcal+w4+DD*DD, ca_b+b4+DD, qkv+DD, 0, 0, DD, QKVLD);
        attn_scores_mma<0><<<gS, 256, SC_DSMEM>>>(qkv, en_pad, sc, pm);
        attn_av_mma<<<gV, 256, AV_DSMEM>>>(sc, pm, qkv, aoh, aol);
        tgemm<0,0,64><<<dim3(DD/128, MM/64), 256, DSM(64)>>>(
            aoh, aol, wcah+w4+3*DD*DD, wcal+w4+3*DD*DD, ca_b+b4+3*DD, pr, 0, 0, DD, DD);
        add_ln<<<MM, 256>>>(h, pr, ln_g+(size_t)(i*3+1)*DD, ln_b+(size_t)(i*3+1)*DD, a, ah, al);
        // feed forward
        tgemm<1,1,128><<<dim3(FFD/128, MM/128), 256, DSM(128)>>>(
            ah, al, wf1h+(size_t)i*FFD*DD, wf1l+(size_t)i*FFD*DD, ff_b1+(size_t)i*FFD,
            0, ffh, ffl, DD, FFD);
        tgemm<0,0,64><<<dim3(DD/128, MM/64), 256, DSM(64)>>>(
            ffh, ffl, wf2h+(size_t)i*FFD*DD, wf2l+(size_t)i*FFD*DD, ff_b2+(size_t)i*DD,
            pr, 0, 0, FFD, DD);
        add_ln<<<MM, 256>>>(a, pr, ln_g+(size_t)(i*3+2)*DD, ln_b+(size_t)(i*3+2)*DD, x, xh, xl);
    }
    tgemm<0,0,128><<<dim3(VV/128, MM/128), 256, DSM(128)>>>(
        xh, xl, woh, wol, out_b, out, 0, 0, DD, VV);
}